// round 1
// baseline (speedup 1.0000x reference)
#include <cuda_runtime.h>

// Problem constants (fixed by setup_inputs)
#define BB 2
#define VV 4
#define NN 2048
#define FF 128
#define EE 32768
#define ETOT 34816   // EE + NN self loops
#define OO 512
#define NCH 68       // ETOT / 512 exactly
#define CHK 512

// Scratch (device globals: allocation-free)
__device__ float g_PQ[(size_t)BB * NN * 8 * OO];   // [b][n][slot 0..3=P0[v],4..7=Q0[v]][o]  64MB
__device__ float g_sA[BB * 16 * NN];
__device__ float g_sB[BB * 16 * NN];
__device__ float g_w[(size_t)ETOT * BB * 16];      // [(e*2+b)*16 + (g*4+h)]
__device__ int   g_src[ETOT];
__device__ int   g_dst[ETOT];
__device__ int   g_rowOff[NN + 1];
__device__ int   g_hist[NCH * NN];
__device__ int   g_csr[ETOT];

// ---------------------------------------------------------------------------
// Edge list incl. self loops
__global__ void k_edges(const int* __restrict__ ei) {
    int e = blockIdx.x * 256 + threadIdx.x;
    if (e >= ETOT) return;
    if (e < EE) { g_src[e] = ei[e]; g_dst[e] = ei[EE + e]; }
    else        { g_src[e] = e - EE; g_dst[e] = e - EE; }
}

// Per-chunk dst histogram (chunk = 512 edges)
__global__ void __launch_bounds__(512) k_hist() {
    __shared__ int sh[NN];
    int t = threadIdx.x;
    for (int i = t; i < NN; i += 512) sh[i] = 0;
    __syncthreads();
    int e = blockIdx.x * CHK + t;
    atomicAdd(&sh[g_dst[e]], 1);
    __syncthreads();
    for (int i = t; i < NN; i += 512) g_hist[blockIdx.x * NN + i] = sh[i];
}

// deg -> rowOff (exclusive scan), and convert hist to per-dst chunk prefix
__global__ void __launch_bounds__(1024) k_scan() {
    __shared__ int sa[NN], sb[NN];
    int t = threadIdx.x;
    int deg[2];
    for (int p = 0; p < 2; p++) {
        int i = t + p * 1024;
        int a = 0;
        for (int ch = 0; ch < NCH; ch++) a += g_hist[ch * NN + i];
        deg[p] = a; sa[i] = a;
    }
    __syncthreads();
    int* A = sa; int* Bf = sb;
    for (int off = 1; off < NN; off <<= 1) {
        for (int p = 0; p < 2; p++) {
            int i = t + p * 1024;
            Bf[i] = A[i] + (i >= off ? A[i - off] : 0);
        }
        __syncthreads();
        int* tmp = A; A = Bf; Bf = tmp;
    }
    for (int p = 0; p < 2; p++) {
        int i = t + p * 1024;
        g_rowOff[i] = A[i] - deg[p];
    }
    if (t == 1023) g_rowOff[NN] = A[NN - 1];
    for (int p = 0; p < 2; p++) {
        int i = t + p * 1024;
        int run = 0;
        for (int ch = 0; ch < NCH; ch++) {
            int h = g_hist[ch * NN + i];
            g_hist[ch * NN + i] = run;
            run += h;
        }
    }
}

// Stable scatter: csr sorted by (dst, e) -> deterministic accumulation order
__global__ void __launch_bounds__(512) k_scatter() {
    __shared__ int base[NN];
    __shared__ int sd[CHK];
    int t = threadIdx.x, ch = blockIdx.x;
    for (int i = t; i < NN; i += 512) base[i] = g_rowOff[i] + g_hist[ch * NN + i];
    sd[t] = g_dst[ch * CHK + t];
    __syncthreads();
    if (t == 0) {
        int e0 = ch * CHK;
        for (int i = 0; i < CHK; i++) {
            int d = sd[i];
            g_csr[base[d]++] = e0 + i;
        }
    }
}

// ---------------------------------------------------------------------------
// Fused GEMM: PQ[b][n][v]   = x[b,v,n,:] @ Wt   (slot v,   cols bx<4)
//             PQ[b][n][4+v] = x[b,v,n,:] @ Wb   (slot 4+v, cols bx>=4)
// M = B*N = 4096 rows per v, Ncols = 1024 = [Wt | Wb], K = 128.
__global__ void __launch_bounds__(256) k_gemm(const float* __restrict__ x,
                                              const float* __restrict__ W) {
    const int v  = blockIdx.z;
    const int bx = blockIdx.x;   // 0..7 (col tiles of 128)
    const int by = blockIdx.y;   // 0..31 (row tiles of 128)
    __shared__ float As[8][128];
    __shared__ float Bs[8][128];
    int tid = threadIdx.x;
    int tr = tid >> 4, tc = tid & 15;
    float acc[8][8];
#pragma unroll
    for (int i = 0; i < 8; i++)
#pragma unroll
        for (int j = 0; j < 8; j++) acc[i][j] = 0.f;

    const float* Wbase = (bx < 4) ? W : (W + 128 * 512);
    int colbase = (bx & 3) * 128;

    int am = tid >> 1, akb = (tid & 1) * 4;
    int m = by * 128 + am;
    int ab = m >> 11, an = m & 2047;
    const float* aptr = x + (((size_t)(ab * 4 + v) * 2048 + an) << 7) + akb;
    int bk = tid >> 5, bc = (tid & 31) * 4;
    const float* bptr = Wbase + (size_t)bk * 512 + colbase + bc;

    for (int kk = 0; kk < 128; kk += 8) {
        float4 fa = *(const float4*)(aptr + kk);
        As[akb + 0][am] = fa.x; As[akb + 1][am] = fa.y;
        As[akb + 2][am] = fa.z; As[akb + 3][am] = fa.w;
        float4 fb = *(const float4*)(bptr + (size_t)kk * 512);
        *(float4*)&Bs[bk][bc] = fb;
        __syncthreads();
#pragma unroll
        for (int k = 0; k < 8; k++) {
            float4 a0 = *(const float4*)&As[k][tr * 8];
            float4 a1 = *(const float4*)&As[k][tr * 8 + 4];
            float4 b0 = *(const float4*)&Bs[k][tc * 8];
            float4 b1 = *(const float4*)&Bs[k][tc * 8 + 4];
            float ra[8] = {a0.x, a0.y, a0.z, a0.w, a1.x, a1.y, a1.z, a1.w};
            float rb[8] = {b0.x, b0.y, b0.z, b0.w, b1.x, b1.y, b1.z, b1.w};
#pragma unroll
            for (int i = 0; i < 8; i++)
#pragma unroll
                for (int j = 0; j < 8; j++) acc[i][j] += ra[i] * rb[j];
        }
        __syncthreads();
    }

    int slot = (bx < 4) ? v : 4 + v;
#pragma unroll
    for (int i = 0; i < 8; i++) {
        int mm = by * 128 + tr * 8 + i;
        int b2 = mm >> 11, n2 = mm & 2047;
        float* dp = g_PQ + (((size_t)(b2 * 2048 + n2) * 8 + slot) << 9) + colbase + tc * 8;
        float4 o0 = make_float4(acc[i][0], acc[i][1], acc[i][2], acc[i][3]);
        float4 o1 = make_float4(acc[i][4], acc[i][5], acc[i][6], acc[i][7]);
        *(float4*)dp = o0;
        *(float4*)(dp + 4) = o1;
    }
}

// ---------------------------------------------------------------------------
// Per-node score components for all 16 combos:
// h_{g,h}[o] = P0[h][o] + Q0[g^h][o] + rank4corr;  sA = sum attA*lrelu(h), sB likewise.
__global__ void __launch_bounds__(512) k_scores(const float* __restrict__ x,
                                                const float* __restrict__ W,
                                                const float* __restrict__ att) {
    __shared__ float shPQ[4096];
    __shared__ float shW[4096];   // [0..2047]=Wt rows0..3, [2048..]=Wb rows0..3
    __shared__ float shAtt[1024];
    int bi = blockIdx.x;
    int b = bi >> 11, n = bi & 2047;
    int tid = threadIdx.x;
    const float* pq = g_PQ + (((size_t)(b * 2048 + n)) << 12);
    for (int i = tid; i < 4096; i += 512) shPQ[i] = pq[i];
    for (int i = tid; i < 2048; i += 512) {
        int j = i >> 9, o = i & 511;
        shW[i] = W[j * 512 + o];
        shW[2048 + i] = W[(128 + j) * 512 + o];
    }
    for (int i = tid; i < 1024; i += 512) shAtt[i] = att[i];
    __syncthreads();

    int c = tid >> 5, lane = tid & 31;
    int g = c >> 2, h = c & 3, r = g ^ h;
    float xh[4], xg[4];
#pragma unroll
    for (int j = 0; j < 4; j++) {
        xh[j] = x[(((b * 4 + h) * 2048 + n) << 7) + j];
        xg[j] = x[(((b * 4 + r) * 2048 + n) << 7) + j];
    }
    float c1 = (r & 1) ? -2.f : 0.f, c2 = (r & 2) ? -2.f : 0.f;
    float c3 = (h & 1) ? -2.f : 0.f, c4 = (h & 2) ? -2.f : 0.f;
    float sa = 0.f, sb = 0.f;
    for (int o = lane; o < 512; o += 32) {
        float hv = shPQ[h * 512 + o] + shPQ[(4 + r) * 512 + o]
                 + c1 * (xh[0] * shW[o]        + xh[2] * shW[1024 + o])
                 + c2 * (xh[1] * shW[512 + o]  + xh[3] * shW[1536 + o])
                 + c3 * (xg[0] * shW[2048 + o] + xg[2] * shW[3072 + o])
                 + c4 * (xg[1] * shW[2560 + o] + xg[3] * shW[3584 + o]);
        float l = hv > 0.f ? hv : 0.2f * hv;
        sa += shAtt[o] * l;
        sb += shAtt[512 + o] * l;
    }
#pragma unroll
    for (int off = 16; off; off >>= 1) {
        sa += __shfl_xor_sync(0xffffffffu, sa, off);
        sb += __shfl_xor_sync(0xffffffffu, sb, off);
    }
    if (lane == 0) {
        g_sA[(b * 16 + c) * 2048 + n] = sa;
        g_sB[(b * 16 + c) * 2048 + n] = sb;
    }
}

// Global softmax over all ETOT edges per (b, combo). One block per (b,c).
__global__ void __launch_bounds__(512) k_softmax() {
    int b = blockIdx.x >> 4, c = blockIdx.x & 15;
    __shared__ float red[512];
    const float* sA = g_sA + (b * 16 + c) * 2048;
    const float* sB = g_sB + (b * 16 + c) * 2048;
    int tid = threadIdx.x;
    float mx = -1e30f;
    for (int e = tid; e < ETOT; e += 512) {
        float s = sA[g_src[e]] + sB[g_dst[e]];
        g_w[(size_t)(e * 2 + b) * 16 + c] = s;
        mx = fmaxf(mx, s);
    }
    red[tid] = mx; __syncthreads();
    for (int st = 256; st > 0; st >>= 1) {
        if (tid < st) red[tid] = fmaxf(red[tid], red[tid + st]);
        __syncthreads();
    }
    mx = red[0]; __syncthreads();
    float sum = 0.f;
    for (int e = tid; e < ETOT; e += 512) {
        size_t idx = (size_t)(e * 2 + b) * 16 + c;
        float w = expf(g_w[idx] - mx);
        g_w[idx] = w;
        sum += w;
    }
    red[tid] = sum; __syncthreads();
    for (int st = 256; st > 0; st >>= 1) {
        if (tid < st) red[tid] += red[tid + st];
        __syncthreads();
    }
    float inv = 1.f / red[0];
    for (int e = tid; e < ETOT; e += 512)
        g_w[(size_t)(e * 2 + b) * 16 + c] *= inv;
}

// ---------------------------------------------------------------------------
// dst-centric aggregation: one block per dst node, thread = output column o.
// out[b,g,d,o] = 0.25 * ( sum_e sum_h w[g,h] (P0[h]+Q0[g^h])[src_e,o] + coef @ Wrows ) + bias[o]
__global__ void __launch_bounds__(512) k_agg(const float* __restrict__ x,
                                             const float* __restrict__ W,
                                             const float* __restrict__ bias,
                                             float* __restrict__ out) {
    int d = blockIdx.x;
    int tid = threadIdx.x;
    __shared__ float sh_w[32];    // [b][g*4+h]
    __shared__ float sh_xs[32];   // [b][v][j]
    __shared__ float sh_coef[64]; // [b][g][j(0..3 Wt,4..7 Wb)]
    if (tid < 64) sh_coef[tid] = 0.f;
    float acc[2][4];
#pragma unroll
    for (int b = 0; b < 2; b++)
#pragma unroll
        for (int g = 0; g < 4; g++) acc[b][g] = 0.f;

    int beg = g_rowOff[d], end = g_rowOff[d + 1];
    for (int idx = beg; idx < end; idx++) {
        __syncthreads();   // protect sh_w/sh_xs from previous iteration's readers
        int e = g_csr[idx];
        int s = g_src[e];
        if (tid < 32) {
            sh_w[tid] = g_w[(size_t)(e * 2 + (tid >> 4)) * 16 + (tid & 15)];
        } else if (tid < 64) {
            int q = tid - 32;
            int b = q >> 4, v = (q >> 2) & 3, j = q & 3;
            sh_xs[q] = x[(((b * 4 + v) * 2048 + s) << 7) + j];
        }
        __syncthreads();
#pragma unroll
        for (int b = 0; b < 2; b++) {
            const float* base = g_PQ + (((size_t)(b * 2048 + s)) << 12) + tid;
            float p0 = base[0],    p1 = base[512],  p2 = base[1024], p3 = base[1536];
            float q0 = base[2048], q1 = base[2560], q2 = base[3072], q3 = base[3584];
            const float* wv = sh_w + b * 16;
            acc[b][0] += wv[0]  * (p0 + q0) + wv[1]  * (p1 + q1) + wv[2]  * (p2 + q2) + wv[3]  * (p3 + q3);
            acc[b][1] += wv[4]  * (p0 + q1) + wv[5]  * (p1 + q0) + wv[6]  * (p2 + q3) + wv[7]  * (p3 + q2);
            acc[b][2] += wv[8]  * (p0 + q2) + wv[9]  * (p1 + q3) + wv[10] * (p2 + q0) + wv[11] * (p3 + q1);
            acc[b][3] += wv[12] * (p0 + q3) + wv[13] * (p1 + q2) + wv[14] * (p2 + q1) + wv[15] * (p3 + q0);
        }
        if (tid < 64) {
            int b = tid >> 5, q5 = tid & 31;
            int g = q5 >> 3, j = q5 & 7, jj = j & 3, isB = j >> 2;
            int mask = (jj == 1 || jj == 3) ? 2 : 1;
            float ca = 0.f;
#pragma unroll
            for (int h = 0; h < 4; h++) {
                int r = isB ? h : (g ^ h);
                if (r & mask) {
                    int vsel = isB ? (g ^ h) : h;
                    ca += sh_w[b * 16 + g * 4 + h] * sh_xs[b * 16 + vsel * 4 + jj];
                }
            }
            sh_coef[tid] -= 2.f * ca;
        }
    }
    __syncthreads();

    float wt0 = W[0 * 512 + tid], wt1 = W[1 * 512 + tid];
    float wt2 = W[2 * 512 + tid], wt3 = W[3 * 512 + tid];
    float wb0 = W[128 * 512 + tid], wb1 = W[129 * 512 + tid];
    float wb2 = W[130 * 512 + tid], wb3 = W[131 * 512 + tid];
    float bs = bias[tid];
#pragma unroll
    for (int b = 0; b < 2; b++)
#pragma unroll
        for (int g = 0; g < 4; g++) {
            const float* cf = sh_coef + b * 32 + g * 8;
            float val = acc[b][g]
                      + cf[0] * wt0 + cf[1] * wt1 + cf[2] * wt2 + cf[3] * wt3
                      + cf[4] * wb0 + cf[5] * wb1 + cf[6] * wb2 + cf[7] * wb3;
            out[(((size_t)(b * 4 + g) * 2048 + d) << 9) + tid] = 0.25f * val + bs;
        }
}

// ---------------------------------------------------------------------------
extern "C" void kernel_launch(void* const* d_in, const int* in_sizes, int n_in,
                              void* d_out, int out_size) {
    const float* x    = (const float*)d_in[0];
    const int*   ei   = (const int*)d_in[1];
    const float* W    = (const float*)d_in[2];
    const float* att  = (const float*)d_in[3];
    const float* bias = (const float*)d_in[4];
    float* out = (float*)d_out;

    k_edges<<<(ETOT + 255) / 256, 256>>>(ei);
    k_hist<<<NCH, CHK>>>();
    k_scan<<<1, 1024>>>();
    k_scatter<<<NCH, CHK>>>();
    k_gemm<<<dim3(8, 32, 4), 256>>>(x, W);
    k_scores<<<BB * NN, 512>>>(x, W, att);
    k_softmax<<<32, 512>>>();
    k_agg<<<NN, 512>>>(x, W, bias, out);
}

// round 2
// speedup vs baseline: 1.5401x; 1.5401x over previous
#include <cuda_runtime.h>

// Problem constants (fixed by setup_inputs)
#define BB 2
#define VV 4
#define NN 2048
#define FF 128
#define EE 32768
#define ETOT 34816   // EE + NN self loops
#define OO 512
#define NCH 68       // ETOT / 512 exactly
#define CHK 512

// Scratch (device globals: allocation-free)
__device__ float g_PQ[(size_t)BB * NN * 8 * OO];   // [b][n][slot 0..3=P0[v],4..7=Q0[v]][o]  64MB
__device__ float g_sA[BB * 16 * NN];
__device__ float g_sB[BB * 16 * NN];
__device__ float g_wt[(size_t)32 * ETOT];          // [(b*16+c)][e]  (softmax out, unnormalized)
__device__ float g_w[(size_t)ETOT * 32];           // [e][b*16+c]    (normalized, agg layout)
__device__ float g_invS[32];
__device__ float g_coef[NN * 64];                  // [d][b][g][j]
__device__ int   g_src[ETOT];
__device__ int   g_dst[ETOT];
__device__ int   g_deg[NN];
__device__ int   g_rowOff[NN + 1];
__device__ int   g_hist[NCH * NN];
__device__ int   g_csr[ETOT];

// ---------------------------------------------------------------------------
// Edge list incl. self loops
__global__ void k_edges(const int* __restrict__ ei) {
    int e = blockIdx.x * 256 + threadIdx.x;
    if (e >= ETOT) return;
    if (e < EE) { g_src[e] = ei[e]; g_dst[e] = ei[EE + e]; }
    else        { g_src[e] = e - EE; g_dst[e] = e - EE; }
}

// Per-chunk dst histogram (chunk = 512 edges)
__global__ void __launch_bounds__(512) k_hist() {
    __shared__ int sh[NN];
    int t = threadIdx.x;
    for (int i = t; i < NN; i += 512) sh[i] = 0;
    __syncthreads();
    int e = blockIdx.x * CHK + t;
    atomicAdd(&sh[g_dst[e]], 1);
    __syncthreads();
    for (int i = t; i < NN; i += 512) g_hist[blockIdx.x * NN + i] = sh[i];
}

// Per-node prefix over chunks, register-resident (full MLP on loads).
__global__ void __launch_bounds__(1024) k_chprefix() {
    int i = blockIdx.x * 1024 + threadIdx.x;   // node
    int v[NCH];
#pragma unroll
    for (int ch = 0; ch < NCH; ch++) v[ch] = g_hist[ch * NN + i];
    int run = 0;
#pragma unroll
    for (int ch = 0; ch < NCH; ch++) { int h = v[ch]; v[ch] = run; run += h; }
#pragma unroll
    for (int ch = 0; ch < NCH; ch++) g_hist[ch * NN + i] = v[ch];
    g_deg[i] = run;
}

// deg -> rowOff (exclusive scan)
__global__ void __launch_bounds__(1024) k_scan() {
    __shared__ int sa[NN], sb[NN];
    int t = threadIdx.x;
    int deg[2];
    for (int p = 0; p < 2; p++) {
        int i = t + p * 1024;
        deg[p] = g_deg[i];
        sa[i] = deg[p];
    }
    __syncthreads();
    int* A = sa; int* Bf = sb;
    for (int off = 1; off < NN; off <<= 1) {
        for (int p = 0; p < 2; p++) {
            int i = t + p * 1024;
            Bf[i] = A[i] + (i >= off ? A[i - off] : 0);
        }
        __syncthreads();
        int* tmp = A; A = Bf; Bf = tmp;
    }
    for (int p = 0; p < 2; p++) {
        int i = t + p * 1024;
        g_rowOff[i] = A[i] - deg[p];
    }
    if (t == 1023) g_rowOff[NN] = A[NN - 1];
}

// Stable scatter, fully parallel: rank = #earlier same-dst edges in chunk.
__global__ void __launch_bounds__(512) k_scatter() {
    __shared__ int base[NN];
    __shared__ int sd[CHK];
    int t = threadIdx.x, ch = blockIdx.x;
    for (int i = t; i < NN; i += 512) base[i] = g_rowOff[i] + g_hist[ch * NN + i];
    int myd = g_dst[ch * CHK + t];
    sd[t] = myd;
    __syncthreads();
    int rank = 0;
    for (int i = 0; i < t; i++) rank += (sd[i] == myd);
    g_csr[base[myd] + rank] = ch * CHK + t;
}

// ---------------------------------------------------------------------------
// Fused GEMM: PQ[b][n][v]   = x[b,v,n,:] @ Wt   (slot v,   cols bx<4)
//             PQ[b][n][4+v] = x[b,v,n,:] @ Wb   (slot 4+v, cols bx>=4)
__global__ void __launch_bounds__(256) k_gemm(const float* __restrict__ x,
                                              const float* __restrict__ W) {
    const int v  = blockIdx.z;
    const int bx = blockIdx.x;   // 0..7 (col tiles of 128)
    const int by = blockIdx.y;   // 0..31 (row tiles of 128)
    __shared__ float As[8][128];
    __shared__ float Bs[8][128];
    int tid = threadIdx.x;
    int tr = tid >> 4, tc = tid & 15;
    float acc[8][8];
#pragma unroll
    for (int i = 0; i < 8; i++)
#pragma unroll
        for (int j = 0; j < 8; j++) acc[i][j] = 0.f;

    const float* Wbase = (bx < 4) ? W : (W + 128 * 512);
    int colbase = (bx & 3) * 128;

    int am = tid >> 1, akb = (tid & 1) * 4;
    int m = by * 128 + am;
    int ab = m >> 11, an = m & 2047;
    const float* aptr = x + (((size_t)(ab * 4 + v) * 2048 + an) << 7) + akb;
    int bk = tid >> 5, bc = (tid & 31) * 4;
    const float* bptr = Wbase + (size_t)bk * 512 + colbase + bc;

    for (int kk = 0; kk < 128; kk += 8) {
        float4 fa = *(const float4*)(aptr + kk);
        As[akb + 0][am] = fa.x; As[akb + 1][am] = fa.y;
        As[akb + 2][am] = fa.z; As[akb + 3][am] = fa.w;
        float4 fb = *(const float4*)(bptr + (size_t)kk * 512);
        *(float4*)&Bs[bk][bc] = fb;
        __syncthreads();
#pragma unroll
        for (int k = 0; k < 8; k++) {
            float4 a0 = *(const float4*)&As[k][tr * 8];
            float4 a1 = *(const float4*)&As[k][tr * 8 + 4];
            float4 b0 = *(const float4*)&Bs[k][tc * 8];
            float4 b1 = *(const float4*)&Bs[k][tc * 8 + 4];
            float ra[8] = {a0.x, a0.y, a0.z, a0.w, a1.x, a1.y, a1.z, a1.w};
            float rb[8] = {b0.x, b0.y, b0.z, b0.w, b1.x, b1.y, b1.z, b1.w};
#pragma unroll
            for (int i = 0; i < 8; i++)
#pragma unroll
                for (int j = 0; j < 8; j++) acc[i][j] += ra[i] * rb[j];
        }
        __syncthreads();
    }

    int slot = (bx < 4) ? v : 4 + v;
#pragma unroll
    for (int i = 0; i < 8; i++) {
        int mm = by * 128 + tr * 8 + i;
        int b2 = mm >> 11, n2 = mm & 2047;
        float* dp = g_PQ + (((size_t)(b2 * 2048 + n2) * 8 + slot) << 9) + colbase + tc * 8;
        float4 o0 = make_float4(acc[i][0], acc[i][1], acc[i][2], acc[i][3]);
        float4 o1 = make_float4(acc[i][4], acc[i][5], acc[i][6], acc[i][7]);
        *(float4*)dp = o0;
        *(float4*)(dp + 4) = o1;
    }
}

// ---------------------------------------------------------------------------
// Per-node score components for all 16 combos.
__global__ void __launch_bounds__(512) k_scores(const float* __restrict__ x,
                                                const float* __restrict__ W,
                                                const float* __restrict__ att) {
    __shared__ float shPQ[4096];
    __shared__ float shW[4096];   // [0..2047]=Wt rows0..3, [2048..]=Wb rows0..3
    __shared__ float shAtt[1024];
    int bi = blockIdx.x;
    int b = bi >> 11, n = bi & 2047;
    int tid = threadIdx.x;
    const float* pq = g_PQ + (((size_t)(b * 2048 + n)) << 12);
    for (int i = tid; i < 4096; i += 512) shPQ[i] = pq[i];
    for (int i = tid; i < 2048; i += 512) {
        int j = i >> 9, o = i & 511;
        shW[i] = W[j * 512 + o];
        shW[2048 + i] = W[(128 + j) * 512 + o];
    }
    for (int i = tid; i < 1024; i += 512) shAtt[i] = att[i];
    __syncthreads();

    int c = tid >> 5, lane = tid & 31;
    int g = c >> 2, h = c & 3, r = g ^ h;
    float xh[4], xg[4];
#pragma unroll
    for (int j = 0; j < 4; j++) {
        xh[j] = x[(((b * 4 + h) * 2048 + n) << 7) + j];
        xg[j] = x[(((b * 4 + r) * 2048 + n) << 7) + j];
    }
    float c1 = (r & 1) ? -2.f : 0.f, c2 = (r & 2) ? -2.f : 0.f;
    float c3 = (h & 1) ? -2.f : 0.f, c4 = (h & 2) ? -2.f : 0.f;
    float sa = 0.f, sb = 0.f;
    for (int o = lane; o < 512; o += 32) {
        float hv = shPQ[h * 512 + o] + shPQ[(4 + r) * 512 + o]
                 + c1 * (xh[0] * shW[o]        + xh[2] * shW[1024 + o])
                 + c2 * (xh[1] * shW[512 + o]  + xh[3] * shW[1536 + o])
                 + c3 * (xg[0] * shW[2048 + o] + xg[2] * shW[3072 + o])
                 + c4 * (xg[1] * shW[2560 + o] + xg[3] * shW[3584 + o]);
        float l = hv > 0.f ? hv : 0.2f * hv;
        sa += shAtt[o] * l;
        sb += shAtt[512 + o] * l;
    }
#pragma unroll
    for (int off = 16; off; off >>= 1) {
        sa += __shfl_xor_sync(0xffffffffu, sa, off);
        sb += __shfl_xor_sync(0xffffffffu, sb, off);
    }
    if (lane == 0) {
        g_sA[(b * 16 + c) * 2048 + n] = sa;
        g_sB[(b * 16 + c) * 2048 + n] = sb;
    }
}

// Softmax: shift by (max sA + max sB) (valid stabilizer), single coalesced
// edge pass writing unnormalized exp into combo-major g_wt, plus 1/sum.
__global__ void __launch_bounds__(512) k_softmax() {
    int b = blockIdx.x >> 4, c = blockIdx.x & 15;
    __shared__ float red[512];
    const float* sA = g_sA + (b * 16 + c) * 2048;
    const float* sB = g_sB + (b * 16 + c) * 2048;
    int tid = threadIdx.x;

    float ma = -1e30f, mb = -1e30f;
    for (int i = tid; i < NN; i += 512) {
        ma = fmaxf(ma, sA[i]);
        mb = fmaxf(mb, sB[i]);
    }
    red[tid] = ma; __syncthreads();
    for (int st = 256; st > 0; st >>= 1) {
        if (tid < st) red[tid] = fmaxf(red[tid], red[tid + st]);
        __syncthreads();
    }
    float mx = red[0]; __syncthreads();
    red[tid] = mb; __syncthreads();
    for (int st = 256; st > 0; st >>= 1) {
        if (tid < st) red[tid] = fmaxf(red[tid], red[tid + st]);
        __syncthreads();
    }
    mx += red[0]; __syncthreads();

    float* wt = g_wt + (size_t)(b * 16 + c) * ETOT;
    float sum = 0.f;
    for (int e = tid; e < ETOT; e += 512) {
        float w = expf(sA[g_src[e]] + sB[g_dst[e]] - mx);
        wt[e] = w;
        sum += w;
    }
    red[tid] = sum; __syncthreads();
    for (int st = 256; st > 0; st >>= 1) {
        if (tid < st) red[tid] += red[tid + st];
        __syncthreads();
    }
    if (tid == 0) g_invS[b * 16 + c] = 1.f / red[0];
}

// Normalize + transpose to [e][b*16+c] layout (full-grid, latency hidden).
__global__ void __launch_bounds__(512) k_norm() {
    __shared__ float inv[32];
    if (threadIdx.x < 32) inv[threadIdx.x] = g_invS[threadIdx.x];
    __syncthreads();
    int t = blockIdx.x * 512 + threadIdx.x;     // 0 .. 32*ETOT-1
    int bc = t / ETOT;
    int e = t - bc * ETOT;
    g_w[(size_t)e * 32 + bc] = g_wt[t] * inv[bc];
}

// Rank-4 correction coefficients per (dst,b,g,j), deterministic csr order.
__global__ void __launch_bounds__(64) k_coef(const float* __restrict__ x) {
    int d = blockIdx.x, tid = threadIdx.x;
    int b = tid >> 5, q = tid & 31;
    int g = q >> 3, j = q & 7, jj = j & 3, isB = j >> 2;
    int mask = (jj & 1) ? 2 : 1;
    float ca = 0.f;
    int beg = g_rowOff[d], end = g_rowOff[d + 1];
    for (int idx = beg; idx < end; idx++) {
        int e = g_csr[idx];
        int s = g_src[e];
#pragma unroll
        for (int h = 0; h < 4; h++) {
            int r = isB ? h : (g ^ h);
            if (r & mask) {
                int vsel = isB ? (g ^ h) : h;
                ca += g_w[(size_t)e * 32 + b * 16 + g * 4 + h]
                    * x[(((b * 4 + vsel) * 2048 + s) << 7) + jj];
            }
        }
    }
    g_coef[d * 64 + tid] = -2.f * ca;
}

// ---------------------------------------------------------------------------
// dst-centric aggregation, barrier-free. Weights fetched once per warp and
// broadcast by shfl; rank-4 corrections come precomputed from k_coef.
__global__ void __launch_bounds__(512, 2) k_agg(const float* __restrict__ W,
                                                const float* __restrict__ bias,
                                                float* __restrict__ out) {
    int d = blockIdx.x;
    int tid = threadIdx.x, lane = tid & 31;
    float acc[2][4];
#pragma unroll
    for (int b = 0; b < 2; b++)
#pragma unroll
        for (int g = 0; g < 4; g++) acc[b][g] = 0.f;

    int beg = g_rowOff[d], end = g_rowOff[d + 1];
    for (int idx = beg; idx < end; idx++) {
        int e = __ldg(&g_csr[idx]);
        int s = __ldg(&g_src[e]);
        float wl = __ldg(g_w + (size_t)e * 32 + lane);   // 32 combo weights across lanes
#pragma unroll
        for (int b = 0; b < 2; b++) {
            const float* base = g_PQ + (((size_t)(b * 2048 + s)) << 12) + tid;
            float p[4], qv[4];
#pragma unroll
            for (int h = 0; h < 4; h++) p[h] = base[h * 512];
#pragma unroll
            for (int h = 0; h < 4; h++) qv[h] = base[2048 + h * 512];
#pragma unroll
            for (int g = 0; g < 4; g++)
#pragma unroll
                for (int h = 0; h < 4; h++) {
                    float w = __shfl_sync(0xffffffffu, wl, b * 16 + g * 4 + h);
                    acc[b][g] = fmaf(w, p[h] + qv[g ^ h], acc[b][g]);
                }
        }
    }

    float wt0 = W[0 * 512 + tid], wt1 = W[1 * 512 + tid];
    float wt2 = W[2 * 512 + tid], wt3 = W[3 * 512 + tid];
    float wb0 = W[128 * 512 + tid], wb1 = W[129 * 512 + tid];
    float wb2 = W[130 * 512 + tid], wb3 = W[131 * 512 + tid];
    float bs = bias[tid];
#pragma unroll
    for (int b = 0; b < 2; b++)
#pragma unroll
        for (int g = 0; g < 4; g++) {
            const float* cf = g_coef + d * 64 + b * 32 + g * 8;
            float val = acc[b][g]
                      + cf[0] * wt0 + cf[1] * wt1 + cf[2] * wt2 + cf[3] * wt3
                      + cf[4] * wb0 + cf[5] * wb1 + cf[6] * wb2 + cf[7] * wb3;
            out[(((size_t)(b * 4 + g) * 2048 + d) << 9) + tid] = 0.25f * val + bs;
        }
}

// ---------------------------------------------------------------------------
extern "C" void kernel_launch(void* const* d_in, const int* in_sizes, int n_in,
                              void* d_out, int out_size) {
    const float* x    = (const float*)d_in[0];
    const int*   ei   = (const int*)d_in[1];
    const float* W    = (const float*)d_in[2];
    const float* att  = (const float*)d_in[3];
    const float* bias = (const float*)d_in[4];
    float* out = (float*)d_out;

    k_edges<<<(ETOT + 255) / 256, 256>>>(ei);
    k_hist<<<NCH, CHK>>>();
    k_chprefix<<<2, 1024>>>();
    k_scan<<<1, 1024>>>();
    k_scatter<<<NCH, CHK>>>();
    k_gemm<<<dim3(8, 32, 4), 256>>>(x, W);
    k_scores<<<BB * NN, 512>>>(x, W, att);
    k_softmax<<<32, 512>>>();
    k_norm<<<(32 * ETOT) / 512, 512>>>();
    k_coef<<<NN, 64>>>(x);
    k_agg<<<NN, 512>>>(W, bias, out);
}

// round 3
// speedup vs baseline: 1.7158x; 1.1141x over previous
#include <cuda_runtime.h>
#include <cuda_bf16.h>

// Problem constants (fixed by setup_inputs)
#define BB 2
#define VV 4
#define NN 2048
#define FF 128
#define EE 32768
#define ETOT 34816   // EE + NN self loops
#define OO 512
#define NCH 68       // ETOT / 512 exactly
#define CHK 512

// Scratch (device globals: allocation-free)
__device__ float g_PQ[(size_t)BB * NN * 8 * OO];   // [b][n][slot 0..3=P0[v],4..7=Q0[v]][o]  64MB
__device__ float g_sA[BB * 16 * NN];
__device__ float g_sB[BB * 16 * NN];
__device__ float g_wt[(size_t)32 * ETOT];          // [(b*16+c)][e]
__device__ float g_w[(size_t)ETOT * 32];           // [e][b*16+c]
__device__ float g_invS[32];
__device__ float g_coef[NN * 64];                  // [d][b][g][j]
__device__ int   g_src[ETOT];
__device__ int   g_dst[ETOT];
__device__ int   g_deg[NN];
__device__ int   g_rowOff[NN + 1];
__device__ int   g_hist[NCH * NN];
__device__ int   g_csr[ETOT];
// bf16 split operands for tensor-core GEMM
__device__ __nv_bfloat16 g_xh[(size_t)BB * VV * NN * FF];
__device__ __nv_bfloat16 g_xl[(size_t)BB * VV * NN * FF];
__device__ __nv_bfloat16 g_WTh[1024 * 128];        // [ncol][k] transposed Wcat
__device__ __nv_bfloat16 g_WTl[1024 * 128];

// ---------------------------------------------------------------------------
__global__ void k_edges(const int* __restrict__ ei) {
    int e = blockIdx.x * 256 + threadIdx.x;
    if (e >= ETOT) return;
    if (e < EE) { g_src[e] = ei[e]; g_dst[e] = ei[EE + e]; }
    else        { g_src[e] = e - EE; g_dst[e] = e - EE; }
}

__global__ void __launch_bounds__(512) k_hist() {
    __shared__ int sh[NN];
    int t = threadIdx.x;
    for (int i = t; i < NN; i += 512) sh[i] = 0;
    __syncthreads();
    int e = blockIdx.x * CHK + t;
    atomicAdd(&sh[g_dst[e]], 1);
    __syncthreads();
    for (int i = t; i < NN; i += 512) g_hist[blockIdx.x * NN + i] = sh[i];
}

__global__ void __launch_bounds__(1024) k_chprefix() {
    int i = blockIdx.x * 1024 + threadIdx.x;
    int v[NCH];
#pragma unroll
    for (int ch = 0; ch < NCH; ch++) v[ch] = g_hist[ch * NN + i];
    int run = 0;
#pragma unroll
    for (int ch = 0; ch < NCH; ch++) { int h = v[ch]; v[ch] = run; run += h; }
#pragma unroll
    for (int ch = 0; ch < NCH; ch++) g_hist[ch * NN + i] = v[ch];
    g_deg[i] = run;
}

__global__ void __launch_bounds__(1024) k_scan() {
    __shared__ int sa[NN], sb[NN];
    int t = threadIdx.x;
    int deg[2];
    for (int p = 0; p < 2; p++) {
        int i = t + p * 1024;
        deg[p] = g_deg[i];
        sa[i] = deg[p];
    }
    __syncthreads();
    int* A = sa; int* Bf = sb;
    for (int off = 1; off < NN; off <<= 1) {
        for (int p = 0; p < 2; p++) {
            int i = t + p * 1024;
            Bf[i] = A[i] + (i >= off ? A[i - off] : 0);
        }
        __syncthreads();
        int* tmp = A; A = Bf; Bf = tmp;
    }
    for (int p = 0; p < 2; p++) {
        int i = t + p * 1024;
        g_rowOff[i] = A[i] - deg[p];
    }
    if (t == 1023) g_rowOff[NN] = A[NN - 1];
}

__global__ void __launch_bounds__(512) k_scatter() {
    __shared__ int base[NN];
    __shared__ int sd[CHK];
    int t = threadIdx.x, ch = blockIdx.x;
    for (int i = t; i < NN; i += 512) base[i] = g_rowOff[i] + g_hist[ch * NN + i];
    int myd = g_dst[ch * CHK + t];
    sd[t] = myd;
    __syncthreads();
    int rank = 0;
    for (int i = 0; i < t; i++) rank += (sd[i] == myd);
    g_csr[base[myd] + rank] = ch * CHK + t;
}

// ---------------------------------------------------------------------------
// bf16 hi/lo splits
__global__ void __launch_bounds__(256) k_splitX(const float* __restrict__ x) {
    int i = blockIdx.x * 256 + threadIdx.x;
    float v = x[i];
    __nv_bfloat16 hi = __float2bfloat16(v);
    g_xh[i] = hi;
    g_xl[i] = __float2bfloat16(v - __bfloat162float(hi));
}

__global__ void __launch_bounds__(256) k_splitW(const float* __restrict__ W) {
    int i = blockIdx.x * 256 + threadIdx.x;   // 0 .. 1024*128-1
    int n = i >> 7, k = i & 127;
    float v = (n < 512) ? W[k * 512 + n] : W[(128 + k) * 512 + (n - 512)];
    __nv_bfloat16 hi = __float2bfloat16(v);
    g_WTh[i] = hi;
    g_WTl[i] = __float2bfloat16(v - __bfloat162float(hi));
}

// ---------------------------------------------------------------------------
// Tensor-core GEMM (bf16 split, fp32 accum): PQ = x @ [Wt|Wb] per view.
// Block tile 128x128, K=128 in 4 chunks of 32; 8 warps (2m x 4n), warp 64x32.
#define SWZ(r, u) (((u) ^ (((r) >> 1) & 3)))
__global__ void __launch_bounds__(256) k_gemm(int dummy) {
    __shared__ __align__(16) unsigned int sAh[128 * 16];
    __shared__ __align__(16) unsigned int sAl[128 * 16];
    __shared__ __align__(16) unsigned int sBh[128 * 16];
    __shared__ __align__(16) unsigned int sBl[128 * 16];

    const int v  = blockIdx.z;
    const int bx = blockIdx.x;   // col tile (128 of 1024)
    const int by = blockIdx.y;   // row tile (128 of 4096)
    int tid = threadIdx.x;
    int lane = tid & 31, wid = tid >> 5;
    int wm = wid & 1, wn = wid >> 1;
    int gq = lane >> 2, tig = lane & 3;

    float acc[4][4][4];
#pragma unroll
    for (int a = 0; a < 4; a++)
#pragma unroll
        for (int b = 0; b < 4; b++)
#pragma unroll
            for (int c = 0; c < 4; c++) acc[a][b][c] = 0.f;

    int lr = tid >> 2, lc = tid & 3;   // loader: row(64/pass), 16B unit

    for (int kc = 0; kc < 4; kc++) {
#pragma unroll
        for (int p = 0; p < 2; p++) {
            int r = lr + p * 64;
            int grow = by * 128 + r;
            int b2 = grow >> 11, n2 = grow & 2047;
            size_t xoff = ((size_t)((b2 * 4 + v) * 2048 + n2)) * 128 + kc * 32 + lc * 8;
            unsigned int widx = r * 16 + (SWZ(r, lc) << 2);
            *(uint4*)&sAh[widx] = *(const uint4*)(g_xh + xoff);
            *(uint4*)&sAl[widx] = *(const uint4*)(g_xl + xoff);
            size_t woff = (size_t)(bx * 128 + r) * 128 + kc * 32 + lc * 8;
            *(uint4*)&sBh[widx] = *(const uint4*)(g_WTh + woff);
            *(uint4*)&sBl[widx] = *(const uint4*)(g_WTl + woff);
        }
        __syncthreads();

#pragma unroll
        for (int k16 = 0; k16 < 2; k16++) {
            int u0 = k16 * 2;
            unsigned int bh[4][2], bl[4][2];
#pragma unroll
            for (int nf = 0; nf < 4; nf++) {
                int br = wn * 32 + nf * 8 + gq;
                bh[nf][0] = sBh[br * 16 + (SWZ(br, u0) << 2) + tig];
                bh[nf][1] = sBh[br * 16 + (SWZ(br, u0 + 1) << 2) + tig];
                bl[nf][0] = sBl[br * 16 + (SWZ(br, u0) << 2) + tig];
                bl[nf][1] = sBl[br * 16 + (SWZ(br, u0 + 1) << 2) + tig];
            }
#pragma unroll
            for (int mf = 0; mf < 4; mf++) {
                int r0 = wm * 64 + mf * 16 + gq;
                int r1 = r0 + 8;
                unsigned int ah0 = sAh[r0 * 16 + (SWZ(r0, u0) << 2) + tig];
                unsigned int ah1 = sAh[r1 * 16 + (SWZ(r1, u0) << 2) + tig];
                unsigned int ah2 = sAh[r0 * 16 + (SWZ(r0, u0 + 1) << 2) + tig];
                unsigned int ah3 = sAh[r1 * 16 + (SWZ(r1, u0 + 1) << 2) + tig];
                unsigned int al0 = sAl[r0 * 16 + (SWZ(r0, u0) << 2) + tig];
                unsigned int al1 = sAl[r1 * 16 + (SWZ(r1, u0) << 2) + tig];
                unsigned int al2 = sAl[r0 * 16 + (SWZ(r0, u0 + 1) << 2) + tig];
                unsigned int al3 = sAl[r1 * 16 + (SWZ(r1, u0 + 1) << 2) + tig];
#pragma unroll
                for (int nf = 0; nf < 4; nf++) {
                    float* c = acc[mf][nf];
                    asm volatile(
                        "mma.sync.aligned.m16n8k16.row.col.f32.bf16.bf16.f32 "
                        "{%0,%1,%2,%3}, {%4,%5,%6,%7}, {%8,%9}, {%0,%1,%2,%3};"
                        : "+f"(c[0]), "+f"(c[1]), "+f"(c[2]), "+f"(c[3])
                        : "r"(ah0), "r"(ah1), "r"(ah2), "r"(ah3),
                          "r"(bh[nf][0]), "r"(bh[nf][1]));
                    asm volatile(
                        "mma.sync.aligned.m16n8k16.row.col.f32.bf16.bf16.f32 "
                        "{%0,%1,%2,%3}, {%4,%5,%6,%7}, {%8,%9}, {%0,%1,%2,%3};"
                        : "+f"(c[0]), "+f"(c[1]), "+f"(c[2]), "+f"(c[3])
                        : "r"(ah0), "r"(ah1), "r"(ah2), "r"(ah3),
                          "r"(bl[nf][0]), "r"(bl[nf][1]));
                    asm volatile(
                        "mma.sync.aligned.m16n8k16.row.col.f32.bf16.bf16.f32 "
                        "{%0,%1,%2,%3}, {%4,%5,%6,%7}, {%8,%9}, {%0,%1,%2,%3};"
                        : "+f"(c[0]), "+f"(c[1]), "+f"(c[2]), "+f"(c[3])
                        : "r"(al0), "r"(al1), "r"(al2), "r"(al3),
                          "r"(bh[nf][0]), "r"(bh[nf][1]));
                }
            }
        }
        __syncthreads();
    }

    // Epilogue: D[g][tig*2..], D[g+8][...]
    int slot0 = (bx < 4) ? v : 4 + v;
    int colb = (bx & 3) * 128;
#pragma unroll
    for (int mf = 0; mf < 4; mf++) {
#pragma unroll
        for (int nf = 0; nf < 4; nf++) {
            int col = colb + wn * 32 + nf * 8 + tig * 2;
            int m0 = by * 128 + wm * 64 + mf * 16 + gq;
            int b2 = m0 >> 11, n2 = m0 & 2047;
            float* dp = g_PQ + (((size_t)(b2 * 2048 + n2) * 8 + slot0) << 9) + col;
            *(float2*)dp = make_float2(acc[mf][nf][0], acc[mf][nf][1]);
            int m1 = m0 + 8;
            int b3 = m1 >> 11, n3 = m1 & 2047;
            float* dp2 = g_PQ + (((size_t)(b3 * 2048 + n3) * 8 + slot0) << 9) + col;
            *(float2*)dp2 = make_float2(acc[mf][nf][2], acc[mf][nf][3]);
        }
    }
}

// ---------------------------------------------------------------------------
__global__ void __launch_bounds__(512) k_scores(const float* __restrict__ x,
                                                const float* __restrict__ W,
                                                const float* __restrict__ att) {
    __shared__ float shPQ[4096];
    __shared__ float shW[4096];
    __shared__ float shAtt[1024];
    int bi = blockIdx.x;
    int b = bi >> 11, n = bi & 2047;
    int tid = threadIdx.x;
    const float* pq = g_PQ + (((size_t)(b * 2048 + n)) << 12);
    for (int i = tid; i < 4096; i += 512) shPQ[i] = pq[i];
    for (int i = tid; i < 2048; i += 512) {
        int j = i >> 9, o = i & 511;
        shW[i] = W[j * 512 + o];
        shW[2048 + i] = W[(128 + j) * 512 + o];
    }
    for (int i = tid; i < 1024; i += 512) shAtt[i] = att[i];
    __syncthreads();

    int c = tid >> 5, lane = tid & 31;
    int g = c >> 2, h = c & 3, r = g ^ h;
    float xh[4], xg[4];
#pragma unroll
    for (int j = 0; j < 4; j++) {
        xh[j] = x[(((b * 4 + h) * 2048 + n) << 7) + j];
        xg[j] = x[(((b * 4 + r) * 2048 + n) << 7) + j];
    }
    float c1 = (r & 1) ? -2.f : 0.f, c2 = (r & 2) ? -2.f : 0.f;
    float c3 = (h & 1) ? -2.f : 0.f, c4 = (h & 2) ? -2.f : 0.f;
    float sa = 0.f, sb = 0.f;
    for (int o = lane; o < 512; o += 32) {
        float hv = shPQ[h * 512 + o] + shPQ[(4 + r) * 512 + o]
                 + c1 * (xh[0] * shW[o]        + xh[2] * shW[1024 + o])
                 + c2 * (xh[1] * shW[512 + o]  + xh[3] * shW[1536 + o])
                 + c3 * (xg[0] * shW[2048 + o] + xg[2] * shW[3072 + o])
                 + c4 * (xg[1] * shW[2560 + o] + xg[3] * shW[3584 + o]);
        float l = hv > 0.f ? hv : 0.2f * hv;
        sa += shAtt[o] * l;
        sb += shAtt[512 + o] * l;
    }
#pragma unroll
    for (int off = 16; off; off >>= 1) {
        sa += __shfl_xor_sync(0xffffffffu, sa, off);
        sb += __shfl_xor_sync(0xffffffffu, sb, off);
    }
    if (lane == 0) {
        g_sA[(b * 16 + c) * 2048 + n] = sa;
        g_sB[(b * 16 + c) * 2048 + n] = sb;
    }
}

__global__ void __launch_bounds__(512) k_softmax() {
    int b = blockIdx.x >> 4, c = blockIdx.x & 15;
    __shared__ float red[512];
    const float* sA = g_sA + (b * 16 + c) * 2048;
    const float* sB = g_sB + (b * 16 + c) * 2048;
    int tid = threadIdx.x;

    float ma = -1e30f, mb = -1e30f;
    for (int i = tid; i < NN; i += 512) {
        ma = fmaxf(ma, sA[i]);
        mb = fmaxf(mb, sB[i]);
    }
    red[tid] = ma; __syncthreads();
    for (int st = 256; st > 0; st >>= 1) {
        if (tid < st) red[tid] = fmaxf(red[tid], red[tid + st]);
        __syncthreads();
    }
    float mx = red[0]; __syncthreads();
    red[tid] = mb; __syncthreads();
    for (int st = 256; st > 0; st >>= 1) {
        if (tid < st) red[tid] = fmaxf(red[tid], red[tid + st]);
        __syncthreads();
    }
    mx += red[0]; __syncthreads();

    float* wt = g_wt + (size_t)(b * 16 + c) * ETOT;
    float sum = 0.f;
    for (int e = tid; e < ETOT; e += 512) {
        float w = expf(sA[g_src[e]] + sB[g_dst[e]] - mx);
        wt[e] = w;
        sum += w;
    }
    red[tid] = sum; __syncthreads();
    for (int st = 256; st > 0; st >>= 1) {
        if (tid < st) red[tid] += red[tid + st];
        __syncthreads();
    }
    if (tid == 0) g_invS[b * 16 + c] = 1.f / red[0];
}

__global__ void __launch_bounds__(512) k_norm() {
    __shared__ float inv[32];
    if (threadIdx.x < 32) inv[threadIdx.x] = g_invS[threadIdx.x];
    __syncthreads();
    int t = blockIdx.x * 512 + threadIdx.x;
    int bc = t / ETOT;
    int e = t - bc * ETOT;
    g_w[(size_t)e * 32 + bc] = g_wt[t] * inv[bc];
}

__global__ void __launch_bounds__(64) k_coef(const float* __restrict__ x) {
    int d = blockIdx.x, tid = threadIdx.x;
    int b = tid >> 5, q = tid & 31;
    int g = q >> 3, j = q & 7, jj = j & 3, isB = j >> 2;
    int mask = (jj & 1) ? 2 : 1;
    float ca = 0.f;
    int beg = g_rowOff[d], end = g_rowOff[d + 1];
    for (int idx = beg; idx < end; idx++) {
        int e = g_csr[idx];
        int s = g_src[e];
#pragma unroll
        for (int h = 0; h < 4; h++) {
            int r = isB ? h : (g ^ h);
            if (r & mask) {
                int vsel = isB ? (g ^ h) : h;
                ca += g_w[(size_t)e * 32 + b * 16 + g * 4 + h]
                    * x[(((b * 4 + vsel) * 2048 + s) << 7) + jj];
            }
        }
    }
    g_coef[d * 64 + tid] = -2.f * ca;
}

// ---------------------------------------------------------------------------
__global__ void __launch_bounds__(512, 2) k_agg(const float* __restrict__ W,
                                                const float* __restrict__ bias,
                                                float* __restrict__ out) {
    int d = blockIdx.x;
    int tid = threadIdx.x, lane = tid & 31;
    float acc[2][4];
#pragma unroll
    for (int b = 0; b < 2; b++)
#pragma unroll
        for (int g = 0; g < 4; g++) acc[b][g] = 0.f;

    int beg = g_rowOff[d], end = g_rowOff[d + 1];
    for (int idx = beg; idx < end; idx++) {
        int e = __ldg(&g_csr[idx]);
        int s = __ldg(&g_src[e]);
        float wl = __ldg(g_w + (size_t)e * 32 + lane);
#pragma unroll
        for (int b = 0; b < 2; b++) {
            const float* base = g_PQ + (((size_t)(b * 2048 + s)) << 12) + tid;
            float p[4], qv[4];
#pragma unroll
            for (int h = 0; h < 4; h++) p[h] = base[h * 512];
#pragma unroll
            for (int h = 0; h < 4; h++) qv[h] = base[2048 + h * 512];
#pragma unroll
            for (int g = 0; g < 4; g++)
#pragma unroll
                for (int h = 0; h < 4; h++) {
                    float w = __shfl_sync(0xffffffffu, wl, b * 16 + g * 4 + h);
                    acc[b][g] = fmaf(w, p[h] + qv[g ^ h], acc[b][g]);
                }
        }
    }

    float wt0 = W[0 * 512 + tid], wt1 = W[1 * 512 + tid];
    float wt2 = W[2 * 512 + tid], wt3 = W[3 * 512 + tid];
    float wb0 = W[128 * 512 + tid], wb1 = W[129 * 512 + tid];
    float wb2 = W[130 * 512 + tid], wb3 = W[131 * 512 + tid];
    float bs = bias[tid];
#pragma unroll
    for (int b = 0; b < 2; b++)
#pragma unroll
        for (int g = 0; g < 4; g++) {
            const float* cf = g_coef + d * 64 + b * 32 + g * 8;
            float val = acc[b][g]
                      + cf[0] * wt0 + cf[1] * wt1 + cf[2] * wt2 + cf[3] * wt3
                      + cf[4] * wb0 + cf[5] * wb1 + cf[6] * wb2 + cf[7] * wb3;
            out[(((size_t)(b * 4 + g) * 2048 + d) << 9) + tid] = 0.25f * val + bs;
        }
}

// ---------------------------------------------------------------------------
extern "C" void kernel_launch(void* const* d_in, const int* in_sizes, int n_in,
                              void* d_out, int out_size) {
    const float* x    = (const float*)d_in[0];
    const int*   ei   = (const int*)d_in[1];
    const float* W    = (const float*)d_in[2];
    const float* att  = (const float*)d_in[3];
    const float* bias = (const float*)d_in[4];
    float* out = (float*)d_out;

    k_edges<<<(ETOT + 255) / 256, 256>>>(ei);
    k_hist<<<NCH, CHK>>>();
    k_chprefix<<<2, 1024>>>();
    k_scan<<<1, 1024>>>();
    k_scatter<<<NCH, CHK>>>();
    k_splitX<<<(BB * VV * NN * FF) / 256, 256>>>(x);
    k_splitW<<<(1024 * 128) / 256, 256>>>(W);
    k_gemm<<<dim3(8, 32, 4), 256>>>(0);
    k_scores<<<BB * NN, 512>>>(x, W, att);
    k_softmax<<<32, 512>>>();
    k_norm<<<(32 * ETOT) / 512, 512>>>();
    k_coef<<<NN, 64>>>(x);
    k_agg<<<NN, 512>>>(W, bias, out);
}

// round 4
// speedup vs baseline: 2.4891x; 1.4507x over previous
#include <cuda_runtime.h>
#include <cuda_bf16.h>
#include <cuda_fp16.h>

// Problem constants (fixed by setup_inputs)
#define BB 2
#define VV 4
#define NN 2048
#define FF 128
#define EE 32768
#define ETOT 34816   // EE + NN self loops
#define OO 512
#define NCH 68       // ETOT / 512 exactly
#define CHK 512
#define ECH 8704     // ETOT / 4

// Scratch (device globals: allocation-free)
__device__ __half g_PQh[(size_t)BB * NN * 8 * OO];  // [b][n][slot][o]  fp16, 32MB
__device__ float g_sA[BB * 16 * NN];
__device__ float g_sB[BB * 16 * NN];
__device__ float g_wt[(size_t)32 * ETOT];           // [(b*16+c)][e]
__device__ float g_w[(size_t)ETOT * 32];            // [e][b*16+c]
__device__ float g_psum[32 * 4];
__device__ float g_invS[32];
__device__ float g_coef[NN * 64];                   // [d][b][g][j]
__device__ int   g_src[ETOT];
__device__ int   g_dst[ETOT];
__device__ int   g_deg[NN];
__device__ int   g_rowOff[NN + 1];
__device__ int   g_hist[NCH * NN];
__device__ int   g_csr[ETOT];
// bf16 split operands for tensor-core GEMM
__device__ __nv_bfloat16 g_xh[(size_t)BB * VV * NN * FF];
__device__ __nv_bfloat16 g_xl[(size_t)BB * VV * NN * FF];
__device__ __nv_bfloat16 g_WTh[1024 * 128];
__device__ __nv_bfloat16 g_WTl[1024 * 128];

// ---------------------------------------------------------------------------
// Edge list + per-chunk dst histogram (fused)
__global__ void __launch_bounds__(512) k_hist(const int* __restrict__ ei) {
    __shared__ int sh[NN];
    int t = threadIdx.x;
    for (int i = t; i < NN; i += 512) sh[i] = 0;
    __syncthreads();
    int e = blockIdx.x * CHK + t;
    int s, d;
    if (e < EE) { s = ei[e]; d = ei[EE + e]; }
    else        { s = e - EE; d = e - EE; }
    g_src[e] = s; g_dst[e] = d;
    atomicAdd(&sh[d], 1);
    __syncthreads();
    for (int i = t; i < NN; i += 512) g_hist[blockIdx.x * NN + i] = sh[i];
}

__global__ void __launch_bounds__(1024) k_chprefix() {
    int i = blockIdx.x * 1024 + threadIdx.x;
    int v[NCH];
#pragma unroll
    for (int ch = 0; ch < NCH; ch++) v[ch] = g_hist[ch * NN + i];
    int run = 0;
#pragma unroll
    for (int ch = 0; ch < NCH; ch++) { int h = v[ch]; v[ch] = run; run += h; }
#pragma unroll
    for (int ch = 0; ch < NCH; ch++) g_hist[ch * NN + i] = v[ch];
    g_deg[i] = run;
}

__global__ void __launch_bounds__(1024) k_scan() {
    __shared__ int sa[NN], sb[NN];
    int t = threadIdx.x;
    int deg[2];
    for (int p = 0; p < 2; p++) {
        int i = t + p * 1024;
        deg[p] = g_deg[i];
        sa[i] = deg[p];
    }
    __syncthreads();
    int* A = sa; int* Bf = sb;
    for (int off = 1; off < NN; off <<= 1) {
        for (int p = 0; p < 2; p++) {
            int i = t + p * 1024;
            Bf[i] = A[i] + (i >= off ? A[i - off] : 0);
        }
        __syncthreads();
        int* tmp = A; A = Bf; Bf = tmp;
    }
    for (int p = 0; p < 2; p++) {
        int i = t + p * 1024;
        g_rowOff[i] = A[i] - deg[p];
    }
    if (t == 1023) g_rowOff[NN] = A[NN - 1];
}

__global__ void __launch_bounds__(512) k_scatter() {
    __shared__ int base[NN];
    __shared__ int sd[CHK];
    int t = threadIdx.x, ch = blockIdx.x;
    for (int i = t; i < NN; i += 512) base[i] = g_rowOff[i] + g_hist[ch * NN + i];
    int myd = g_dst[ch * CHK + t];
    sd[t] = myd;
    __syncthreads();
    int rank = 0;
    for (int i = 0; i < t; i++) rank += (sd[i] == myd);
    g_csr[base[myd] + rank] = ch * CHK + t;
}

// ---------------------------------------------------------------------------
__global__ void __launch_bounds__(256) k_splitX(const float* __restrict__ x) {
    int i = blockIdx.x * 256 + threadIdx.x;
    float v = x[i];
    __nv_bfloat16 hi = __float2bfloat16(v);
    g_xh[i] = hi;
    g_xl[i] = __float2bfloat16(v - __bfloat162float(hi));
}

__global__ void __launch_bounds__(256) k_splitW(const float* __restrict__ W) {
    int i = blockIdx.x * 256 + threadIdx.x;
    int n = i >> 7, k = i & 127;
    float v = (n < 512) ? W[k * 512 + n] : W[(128 + k) * 512 + (n - 512)];
    __nv_bfloat16 hi = __float2bfloat16(v);
    g_WTh[i] = hi;
    g_WTl[i] = __float2bfloat16(v - __bfloat162float(hi));
}

// ---------------------------------------------------------------------------
// Tensor-core GEMM (bf16 split, fp32 accum), fp16 output.
#define SWZ(r, u) (((u) ^ (((r) >> 1) & 3)))
__global__ void __launch_bounds__(256) k_gemm(int dummy) {
    __shared__ __align__(16) unsigned int sAh[128 * 16];
    __shared__ __align__(16) unsigned int sAl[128 * 16];
    __shared__ __align__(16) unsigned int sBh[128 * 16];
    __shared__ __align__(16) unsigned int sBl[128 * 16];

    const int v  = blockIdx.z;
    const int bx = blockIdx.x;
    const int by = blockIdx.y;
    int tid = threadIdx.x;
    int lane = tid & 31, wid = tid >> 5;
    int wm = wid & 1, wn = wid >> 1;
    int gq = lane >> 2, tig = lane & 3;

    float acc[4][4][4];
#pragma unroll
    for (int a = 0; a < 4; a++)
#pragma unroll
        for (int b = 0; b < 4; b++)
#pragma unroll
            for (int c = 0; c < 4; c++) acc[a][b][c] = 0.f;

    int lr = tid >> 2, lc = tid & 3;

    for (int kc = 0; kc < 4; kc++) {
#pragma unroll
        for (int p = 0; p < 2; p++) {
            int r = lr + p * 64;
            int grow = by * 128 + r;
            int b2 = grow >> 11, n2 = grow & 2047;
            size_t xoff = ((size_t)((b2 * 4 + v) * 2048 + n2)) * 128 + kc * 32 + lc * 8;
            unsigned int widx = r * 16 + (SWZ(r, lc) << 2);
            *(uint4*)&sAh[widx] = *(const uint4*)(g_xh + xoff);
            *(uint4*)&sAl[widx] = *(const uint4*)(g_xl + xoff);
            size_t woff = (size_t)(bx * 128 + r) * 128 + kc * 32 + lc * 8;
            *(uint4*)&sBh[widx] = *(const uint4*)(g_WTh + woff);
            *(uint4*)&sBl[widx] = *(const uint4*)(g_WTl + woff);
        }
        __syncthreads();

#pragma unroll
        for (int k16 = 0; k16 < 2; k16++) {
            int u0 = k16 * 2;
            unsigned int bh[4][2], bl[4][2];
#pragma unroll
            for (int nf = 0; nf < 4; nf++) {
                int br = wn * 32 + nf * 8 + gq;
                bh[nf][0] = sBh[br * 16 + (SWZ(br, u0) << 2) + tig];
                bh[nf][1] = sBh[br * 16 + (SWZ(br, u0 + 1) << 2) + tig];
                bl[nf][0] = sBl[br * 16 + (SWZ(br, u0) << 2) + tig];
                bl[nf][1] = sBl[br * 16 + (SWZ(br, u0 + 1) << 2) + tig];
            }
#pragma unroll
            for (int mf = 0; mf < 4; mf++) {
                int r0 = wm * 64 + mf * 16 + gq;
                int r1 = r0 + 8;
                unsigned int ah0 = sAh[r0 * 16 + (SWZ(r0, u0) << 2) + tig];
                unsigned int ah1 = sAh[r1 * 16 + (SWZ(r1, u0) << 2) + tig];
                unsigned int ah2 = sAh[r0 * 16 + (SWZ(r0, u0 + 1) << 2) + tig];
                unsigned int ah3 = sAh[r1 * 16 + (SWZ(r1, u0 + 1) << 2) + tig];
                unsigned int al0 = sAl[r0 * 16 + (SWZ(r0, u0) << 2) + tig];
                unsigned int al1 = sAl[r1 * 16 + (SWZ(r1, u0) << 2) + tig];
                unsigned int al2 = sAl[r0 * 16 + (SWZ(r0, u0 + 1) << 2) + tig];
                unsigned int al3 = sAl[r1 * 16 + (SWZ(r1, u0 + 1) << 2) + tig];
#pragma unroll
                for (int nf = 0; nf < 4; nf++) {
                    float* c = acc[mf][nf];
                    asm volatile(
                        "mma.sync.aligned.m16n8k16.row.col.f32.bf16.bf16.f32 "
                        "{%0,%1,%2,%3}, {%4,%5,%6,%7}, {%8,%9}, {%0,%1,%2,%3};"
                        : "+f"(c[0]), "+f"(c[1]), "+f"(c[2]), "+f"(c[3])
                        : "r"(ah0), "r"(ah1), "r"(ah2), "r"(ah3),
                          "r"(bh[nf][0]), "r"(bh[nf][1]));
                    asm volatile(
                        "mma.sync.aligned.m16n8k16.row.col.f32.bf16.bf16.f32 "
                        "{%0,%1,%2,%3}, {%4,%5,%6,%7}, {%8,%9}, {%0,%1,%2,%3};"
                        : "+f"(c[0]), "+f"(c[1]), "+f"(c[2]), "+f"(c[3])
                        : "r"(ah0), "r"(ah1), "r"(ah2), "r"(ah3),
                          "r"(bl[nf][0]), "r"(bl[nf][1]));
                    asm volatile(
                        "mma.sync.aligned.m16n8k16.row.col.f32.bf16.bf16.f32 "
                        "{%0,%1,%2,%3}, {%4,%5,%6,%7}, {%8,%9}, {%0,%1,%2,%3};"
                        : "+f"(c[0]), "+f"(c[1]), "+f"(c[2]), "+f"(c[3])
                        : "r"(al0), "r"(al1), "r"(al2), "r"(al3),
                          "r"(bh[nf][0]), "r"(bh[nf][1]));
                }
            }
        }
        __syncthreads();
    }

    int slot0 = (bx < 4) ? v : 4 + v;
    int colb = (bx & 3) * 128;
#pragma unroll
    for (int mf = 0; mf < 4; mf++) {
#pragma unroll
        for (int nf = 0; nf < 4; nf++) {
            int col = colb + wn * 32 + nf * 8 + tig * 2;
            int m0 = by * 128 + wm * 64 + mf * 16 + gq;
            int b2 = m0 >> 11, n2 = m0 & 2047;
            __half* dp = g_PQh + (((size_t)(b2 * 2048 + n2) * 8 + slot0) << 9) + col;
            *(__half2*)dp = __floats2half2_rn(acc[mf][nf][0], acc[mf][nf][1]);
            int m1 = m0 + 8;
            int b3 = m1 >> 11, n3 = m1 & 2047;
            __half* dp2 = g_PQh + (((size_t)(b3 * 2048 + n3) * 8 + slot0) << 9) + col;
            *(__half2*)dp2 = __floats2half2_rn(acc[mf][nf][2], acc[mf][nf][3]);
        }
    }
}

// ---------------------------------------------------------------------------
__global__ void __launch_bounds__(512) k_scores(const float* __restrict__ x,
                                                const float* __restrict__ W,
                                                const float* __restrict__ att) {
    __shared__ float shPQ[4096];
    __shared__ float shW[4096];
    __shared__ float shAtt[1024];
    int bi = blockIdx.x;
    int b = bi >> 11, n = bi & 2047;
    int tid = threadIdx.x;
    const __half2* pq = (const __half2*)(g_PQh + (((size_t)(b * 2048 + n)) << 12));
    for (int i = tid; i < 2048; i += 512) {
        float2 f = __half22float2(pq[i]);
        shPQ[2 * i] = f.x; shPQ[2 * i + 1] = f.y;
    }
    for (int i = tid; i < 2048; i += 512) {
        int j = i >> 9, o = i & 511;
        shW[i] = W[j * 512 + o];
        shW[2048 + i] = W[(128 + j) * 512 + o];
    }
    for (int i = tid; i < 1024; i += 512) shAtt[i] = att[i];
    __syncthreads();

    int c = tid >> 5, lane = tid & 31;
    int g = c >> 2, h = c & 3, r = g ^ h;
    float xh[4], xg[4];
#pragma unroll
    for (int j = 0; j < 4; j++) {
        xh[j] = x[(((b * 4 + h) * 2048 + n) << 7) + j];
        xg[j] = x[(((b * 4 + r) * 2048 + n) << 7) + j];
    }
    float c1 = (r & 1) ? -2.f : 0.f, c2 = (r & 2) ? -2.f : 0.f;
    float c3 = (h & 1) ? -2.f : 0.f, c4 = (h & 2) ? -2.f : 0.f;
    float sa = 0.f, sb = 0.f;
    for (int o = lane; o < 512; o += 32) {
        float hv = shPQ[h * 512 + o] + shPQ[(4 + r) * 512 + o]
                 + c1 * (xh[0] * shW[o]        + xh[2] * shW[1024 + o])
                 + c2 * (xh[1] * shW[512 + o]  + xh[3] * shW[1536 + o])
                 + c3 * (xg[0] * shW[2048 + o] + xg[2] * shW[3072 + o])
                 + c4 * (xg[1] * shW[2560 + o] + xg[3] * shW[3584 + o]);
        float l = hv > 0.f ? hv : 0.2f * hv;
        sa += shAtt[o] * l;
        sb += shAtt[512 + o] * l;
    }
#pragma unroll
    for (int off = 16; off; off >>= 1) {
        sa += __shfl_xor_sync(0xffffffffu, sa, off);
        sb += __shfl_xor_sync(0xffffffffu, sb, off);
    }
    if (lane == 0) {
        g_sA[(b * 16 + c) * 2048 + n] = sa;
        g_sB[(b * 16 + c) * 2048 + n] = sb;
    }
}

// exp pass, 4-way edge-parallel per combo; each block computes the cheap
// node-max itself. Writes unnormalized exp + partial sums.
__global__ void __launch_bounds__(512) k_exp() {
    int bc = blockIdx.x >> 2, ch = blockIdx.x & 3;
    __shared__ float red[512];
    const float* sA = g_sA + bc * 2048;
    const float* sB = g_sB + bc * 2048;
    int tid = threadIdx.x;

    float ma = -1e30f, mb = -1e30f;
    for (int i = tid; i < NN; i += 512) {
        ma = fmaxf(ma, sA[i]);
        mb = fmaxf(mb, sB[i]);
    }
    red[tid] = ma; __syncthreads();
    for (int st = 256; st > 0; st >>= 1) {
        if (tid < st) red[tid] = fmaxf(red[tid], red[tid + st]);
        __syncthreads();
    }
    float mx = red[0]; __syncthreads();
    red[tid] = mb; __syncthreads();
    for (int st = 256; st > 0; st >>= 1) {
        if (tid < st) red[tid] = fmaxf(red[tid], red[tid + st]);
        __syncthreads();
    }
    mx += red[0]; __syncthreads();

    float* wt = g_wt + (size_t)bc * ETOT;
    float sum = 0.f;
    int e0 = ch * ECH;
#pragma unroll 4
    for (int k = 0; k < ECH / 512; k++) {
        int e = e0 + k * 512 + tid;
        float w = expf(sA[g_src[e]] + sB[g_dst[e]] - mx);
        wt[e] = w;
        sum += w;
    }
    red[tid] = sum; __syncthreads();
    for (int st = 256; st > 0; st >>= 1) {
        if (tid < st) red[tid] += red[tid + st];
        __syncthreads();
    }
    if (tid == 0) g_psum[bc * 4 + ch] = red[0];
}

__global__ void k_sumS() {
    int bc = threadIdx.x;   // 32 threads
    float s = g_psum[bc * 4] + g_psum[bc * 4 + 1] + g_psum[bc * 4 + 2] + g_psum[bc * 4 + 3];
    g_invS[bc] = 1.f / s;
}

__global__ void __launch_bounds__(512) k_norm() {
    __shared__ float inv[32];
    if (threadIdx.x < 32) inv[threadIdx.x] = g_invS[threadIdx.x];
    __syncthreads();
    int t = blockIdx.x * 512 + threadIdx.x;
    int bc = t / ETOT;
    int e = t - bc * ETOT;
    g_w[(size_t)e * 32 + bc] = g_wt[t] * inv[bc];
}

__global__ void __launch_bounds__(64) k_coef(const float* __restrict__ x) {
    int d = blockIdx.x, tid = threadIdx.x;
    int b = tid >> 5, q = tid & 31;
    int g = q >> 3, j = q & 7, jj = j & 3, isB = j >> 2;
    int mask = (jj & 1) ? 2 : 1;
    float ca = 0.f;
    int beg = g_rowOff[d], end = g_rowOff[d + 1];
    for (int idx = beg; idx < end; idx++) {
        int e = g_csr[idx];
        int s = g_src[e];
#pragma unroll
        for (int h = 0; h < 4; h++) {
            int r = isB ? h : (g ^ h);
            if (r & mask) {
                int vsel = isB ? (g ^ h) : h;
                ca += g_w[(size_t)e * 32 + b * 16 + g * 4 + h]
                    * x[(((b * 4 + vsel) * 2048 + s) << 7) + jj];
            }
        }
    }
    g_coef[d * 64 + tid] = -2.f * ca;
}

// ---------------------------------------------------------------------------
// dst-centric aggregation, fp16 gathers (half2 col pairs), edge list in smem.
__global__ void __launch_bounds__(256, 4) k_agg(const float* __restrict__ W,
                                                const float* __restrict__ bias,
                                                float* __restrict__ out) {
    int d = blockIdx.x;
    int tid = threadIdx.x, lane = tid & 31;
    __shared__ int sh_e[512];
    __shared__ int sh_s[512];
    __shared__ float sh_cf[64];

    int beg = g_rowOff[d];
    int deg = g_rowOff[d + 1] - beg;
    for (int i = tid; i < deg; i += 256) {
        int e = g_csr[beg + i];
        sh_e[i] = e;
        sh_s[i] = g_src[e];
    }
    if (tid < 64) sh_cf[tid] = g_coef[d * 64 + tid];
    __syncthreads();

    float accx[2][4], accy[2][4];
#pragma unroll
    for (int b = 0; b < 2; b++)
#pragma unroll
        for (int g = 0; g < 4; g++) { accx[b][g] = 0.f; accy[b][g] = 0.f; }

    for (int i = 0; i < deg; i++) {
        int e = sh_e[i], s = sh_s[i];
        float wl = __ldg(g_w + (size_t)e * 32 + lane);
#pragma unroll
        for (int b = 0; b < 2; b++) {
            const __half2* base = (const __half2*)(g_PQh + (((size_t)(b * 2048 + s)) << 12)) + tid;
            float2 p[4], qv[4];
#pragma unroll
            for (int h = 0; h < 4; h++) p[h] = __half22float2(__ldg(base + h * 256));
#pragma unroll
            for (int h = 0; h < 4; h++) qv[h] = __half22float2(__ldg(base + 1024 + h * 256));
            // all 16 (h, j) sums, each used once across g
            float sx[4][4], sy[4][4];
#pragma unroll
            for (int h = 0; h < 4; h++)
#pragma unroll
                for (int j = 0; j < 4; j++) {
                    sx[h][j] = p[h].x + qv[j].x;
                    sy[h][j] = p[h].y + qv[j].y;
                }
#pragma unroll
            for (int g = 0; g < 4; g++)
#pragma unroll
                for (int h = 0; h < 4; h++) {
                    float w = __shfl_sync(0xffffffffu, wl, b * 16 + g * 4 + h);
                    accx[b][g] = fmaf(w, sx[h][g ^ h], accx[b][g]);
                    accy[b][g] = fmaf(w, sy[h][g ^ h], accy[b][g]);
                }
        }
    }

    int c0 = 2 * tid;
    float2 wt0 = *(const float2*)(W + 0 * 512 + c0);
    float2 wt1 = *(const float2*)(W + 1 * 512 + c0);
    float2 wt2 = *(const float2*)(W + 2 * 512 + c0);
    float2 wt3 = *(const float2*)(W + 3 * 512 + c0);
    float2 wb0 = *(const float2*)(W + 128 * 512 + c0);
    float2 wb1 = *(const float2*)(W + 129 * 512 + c0);
    float2 wb2 = *(const float2*)(W + 130 * 512 + c0);
    float2 wb3 = *(const float2*)(W + 131 * 512 + c0);
    float2 bs = *(const float2*)(bias + c0);
#pragma unroll
    for (int b = 0; b < 2; b++)
#pragma unroll
        for (int g = 0; g < 4; g++) {
            const float* cf = sh_cf + b * 32 + g * 8;
            float vx = accx[b][g]
                     + cf[0] * wt0.x + cf[1] * wt1.x + cf[2] * wt2.x + cf[3] * wt3.x
                     + cf[4] * wb0.x + cf[5] * wb1.x + cf[6] * wb2.x + cf[7] * wb3.x;
            float vy = accy[b][g]
                     + cf[0] * wt0.y + cf[1] * wt1.y + cf[2] * wt2.y + cf[3] * wt3.y
                     + cf[4] * wb0.y + cf[5] * wb1.y + cf[6] * wb2.y + cf[7] * wb3.y;
            float2 o = make_float2(0.25f * vx + bs.x, 0.25f * vy + bs.y);
            *(float2*)(out + (((size_t)(b * 4 + g) * 2048 + d) << 9) + c0) = o;
        }
}

// ---------------------------------------------------------------------------
extern "C" void kernel_launch(void* const* d_in, const int* in_sizes, int n_in,
                              void* d_out, int out_size) {
    const float* x    = (const float*)d_in[0];
    const int*   ei   = (const int*)d_in[1];
    const float* W    = (const float*)d_in[2];
    const float* att  = (const float*)d_in[3];
    const float* bias = (const float*)d_in[4];
    float* out = (float*)d_out;

    k_hist<<<NCH, CHK>>>(ei);
    k_chprefix<<<2, 1024>>>();
    k_scan<<<1, 1024>>>();
    k_scatter<<<NCH, CHK>>>();
    k_splitX<<<(BB * VV * NN * FF) / 256, 256>>>(x);
    k_splitW<<<(1024 * 128) / 256, 256>>>(W);
    k_gemm<<<dim3(8, 32, 4), 256>>>(0);
    k_scores<<<BB * NN, 512>>>(x, W, att);
    k_exp<<<128, 512>>>();
    k_sumS<<<1, 32>>>();
    k_norm<<<(32 * ETOT) / 512, 512>>>();
    k_coef<<<NN, 64>>>(x);
    k_agg<<<NN, 256>>>(W, bias, out);
}

// round 5
// speedup vs baseline: 2.6809x; 1.0770x over previous
#include <cuda_runtime.h>
#include <cuda_bf16.h>
#include <cuda_fp16.h>

// Problem constants (fixed by setup_inputs)
#define BB 2
#define VV 4
#define NN 2048
#define FF 128
#define EE 32768
#define ETOT 34816   // EE + NN self loops
#define OO 512
#define NCH 68       // ETOT / 512 exactly
#define CHK 512
#define ECH 8704     // ETOT / 4

// Scratch (device globals: allocation-free)
__device__ __half g_PQh[(size_t)BB * NN * 8 * OO];  // [b][n][slot][o]  fp16, 32MB
__device__ float g_sA[BB * 16 * NN];
__device__ float g_sB[BB * 16 * NN];
__device__ float g_wt[(size_t)32 * ETOT];           // [(b*16+c)][e]
__device__ float g_w[(size_t)ETOT * 32];            // [e][b*16+c]
__device__ float g_psum[32 * 4];
__device__ float g_invS[32];
__device__ float g_coef[NN * 64];                   // [d][b][g][j]
__device__ int   g_src[ETOT];
__device__ int   g_dst[ETOT];
__device__ int   g_deg[NN];
__device__ int   g_rowOff[NN + 1];
__device__ int   g_hist[NCH * NN];
__device__ int   g_csr[ETOT];
// bf16 split operands for tensor-core GEMM
__device__ __nv_bfloat16 g_xh[(size_t)BB * VV * NN * FF];
__device__ __nv_bfloat16 g_xl[(size_t)BB * VV * NN * FF];
__device__ __nv_bfloat16 g_WTh[1024 * 128];
__device__ __nv_bfloat16 g_WTl[1024 * 128];

// ---------------------------------------------------------------------------
// Edge list + per-chunk dst histogram (fused)
__global__ void __launch_bounds__(512) k_hist(const int* __restrict__ ei) {
    __shared__ int sh[NN];
    int t = threadIdx.x;
    for (int i = t; i < NN; i += 512) sh[i] = 0;
    __syncthreads();
    int e = blockIdx.x * CHK + t;
    int s, d;
    if (e < EE) { s = ei[e]; d = ei[EE + e]; }
    else        { s = e - EE; d = e - EE; }
    g_src[e] = s; g_dst[e] = d;
    atomicAdd(&sh[d], 1);
    __syncthreads();
    for (int i = t; i < NN; i += 512) g_hist[blockIdx.x * NN + i] = sh[i];
}

__global__ void __launch_bounds__(1024) k_chprefix() {
    int i = blockIdx.x * 1024 + threadIdx.x;
    int v[NCH];
#pragma unroll
    for (int ch = 0; ch < NCH; ch++) v[ch] = g_hist[ch * NN + i];
    int run = 0;
#pragma unroll
    for (int ch = 0; ch < NCH; ch++) { int h = v[ch]; v[ch] = run; run += h; }
#pragma unroll
    for (int ch = 0; ch < NCH; ch++) g_hist[ch * NN + i] = v[ch];
    g_deg[i] = run;
}

__global__ void __launch_bounds__(1024) k_scan() {
    __shared__ int sa[NN], sb[NN];
    int t = threadIdx.x;
    int deg[2];
    for (int p = 0; p < 2; p++) {
        int i = t + p * 1024;
        deg[p] = g_deg[i];
        sa[i] = deg[p];
    }
    __syncthreads();
    int* A = sa; int* Bf = sb;
    for (int off = 1; off < NN; off <<= 1) {
        for (int p = 0; p < 2; p++) {
            int i = t + p * 1024;
            Bf[i] = A[i] + (i >= off ? A[i - off] : 0);
        }
        __syncthreads();
        int* tmp = A; A = Bf; Bf = tmp;
    }
    for (int p = 0; p < 2; p++) {
        int i = t + p * 1024;
        g_rowOff[i] = A[i] - deg[p];
    }
    if (t == 1023) g_rowOff[NN] = A[NN - 1];
}

// Stable scatter via warp-cooperative ranking (same (dst,e) order as serial).
__global__ void __launch_bounds__(512) k_scatter() {
    __shared__ int base[NN];
    __shared__ int cnt[NN];
    int t = threadIdx.x, ch = blockIdx.x;
    for (int i = t; i < NN; i += 512) {
        base[i] = g_rowOff[i] + g_hist[ch * NN + i];
        cnt[i] = 0;
    }
    int e = ch * CHK + t;
    int myd = g_dst[e];
    int lane = t & 31, wid = t >> 5;
    __syncthreads();
    unsigned mask = __match_any_sync(0xffffffffu, myd);
    int rin = __popc(mask & ((1u << lane) - 1));
    int leader = __ffs(mask) - 1;
    int gcnt = __popc(mask);
#pragma unroll 1
    for (int w = 0; w < 16; w++) {
        if (wid == w) {
            int prior = cnt[myd];
            g_csr[base[myd] + prior + rin] = e;
            if (lane == leader) cnt[myd] = prior + gcnt;
        }
        __syncthreads();
    }
}

// ---------------------------------------------------------------------------
__global__ void __launch_bounds__(256) k_splitX(const float* __restrict__ x) {
    int i = blockIdx.x * 256 + threadIdx.x;
    float v = x[i];
    __nv_bfloat16 hi = __float2bfloat16(v);
    g_xh[i] = hi;
    g_xl[i] = __float2bfloat16(v - __bfloat162float(hi));
}

__global__ void __launch_bounds__(256) k_splitW(const float* __restrict__ W) {
    int i = blockIdx.x * 256 + threadIdx.x;
    int n = i >> 7, k = i & 127;
    float v = (n < 512) ? W[k * 512 + n] : W[(128 + k) * 512 + (n - 512)];
    __nv_bfloat16 hi = __float2bfloat16(v);
    g_WTh[i] = hi;
    g_WTl[i] = __float2bfloat16(v - __bfloat162float(hi));
}

// ---------------------------------------------------------------------------
// Tensor-core GEMM (bf16 split, fp32 accum), fp16 output.
#define SWZ(r, u) (((u) ^ (((r) >> 1) & 3)))
__global__ void __launch_bounds__(256) k_gemm(int dummy) {
    __shared__ __align__(16) unsigned int sAh[128 * 16];
    __shared__ __align__(16) unsigned int sAl[128 * 16];
    __shared__ __align__(16) unsigned int sBh[128 * 16];
    __shared__ __align__(16) unsigned int sBl[128 * 16];

    const int v  = blockIdx.z;
    const int bx = blockIdx.x;
    const int by = blockIdx.y;
    int tid = threadIdx.x;
    int lane = tid & 31, wid = tid >> 5;
    int wm = wid & 1, wn = wid >> 1;
    int gq = lane >> 2, tig = lane & 3;

    float acc[4][4][4];
#pragma unroll
    for (int a = 0; a < 4; a++)
#pragma unroll
        for (int b = 0; b < 4; b++)
#pragma unroll
            for (int c = 0; c < 4; c++) acc[a][b][c] = 0.f;

    int lr = tid >> 2, lc = tid & 3;

    for (int kc = 0; kc < 4; kc++) {
#pragma unroll
        for (int p = 0; p < 2; p++) {
            int r = lr + p * 64;
            int grow = by * 128 + r;
            int b2 = grow >> 11, n2 = grow & 2047;
            size_t xoff = ((size_t)((b2 * 4 + v) * 2048 + n2)) * 128 + kc * 32 + lc * 8;
            unsigned int widx = r * 16 + (SWZ(r, lc) << 2);
            *(uint4*)&sAh[widx] = *(const uint4*)(g_xh + xoff);
            *(uint4*)&sAl[widx] = *(const uint4*)(g_xl + xoff);
            size_t woff = (size_t)(bx * 128 + r) * 128 + kc * 32 + lc * 8;
            *(uint4*)&sBh[widx] = *(const uint4*)(g_WTh + woff);
            *(uint4*)&sBl[widx] = *(const uint4*)(g_WTl + woff);
        }
        __syncthreads();

#pragma unroll
        for (int k16 = 0; k16 < 2; k16++) {
            int u0 = k16 * 2;
            unsigned int bh[4][2], bl[4][2];
#pragma unroll
            for (int nf = 0; nf < 4; nf++) {
                int br = wn * 32 + nf * 8 + gq;
                bh[nf][0] = sBh[br * 16 + (SWZ(br, u0) << 2) + tig];
                bh[nf][1] = sBh[br * 16 + (SWZ(br, u0 + 1) << 2) + tig];
                bl[nf][0] = sBl[br * 16 + (SWZ(br, u0) << 2) + tig];
                bl[nf][1] = sBl[br * 16 + (SWZ(br, u0 + 1) << 2) + tig];
            }
#pragma unroll
            for (int mf = 0; mf < 4; mf++) {
                int r0 = wm * 64 + mf * 16 + gq;
                int r1 = r0 + 8;
                unsigned int ah0 = sAh[r0 * 16 + (SWZ(r0, u0) << 2) + tig];
                unsigned int ah1 = sAh[r1 * 16 + (SWZ(r1, u0) << 2) + tig];
                unsigned int ah2 = sAh[r0 * 16 + (SWZ(r0, u0 + 1) << 2) + tig];
                unsigned int ah3 = sAh[r1 * 16 + (SWZ(r1, u0 + 1) << 2) + tig];
                unsigned int al0 = sAl[r0 * 16 + (SWZ(r0, u0) << 2) + tig];
                unsigned int al1 = sAl[r1 * 16 + (SWZ(r1, u0) << 2) + tig];
                unsigned int al2 = sAl[r0 * 16 + (SWZ(r0, u0 + 1) << 2) + tig];
                unsigned int al3 = sAl[r1 * 16 + (SWZ(r1, u0 + 1) << 2) + tig];
#pragma unroll
                for (int nf = 0; nf < 4; nf++) {
                    float* c = acc[mf][nf];
                    asm volatile(
                        "mma.sync.aligned.m16n8k16.row.col.f32.bf16.bf16.f32 "
                        "{%0,%1,%2,%3}, {%4,%5,%6,%7}, {%8,%9}, {%0,%1,%2,%3};"
                        : "+f"(c[0]), "+f"(c[1]), "+f"(c[2]), "+f"(c[3])
                        : "r"(ah0), "r"(ah1), "r"(ah2), "r"(ah3),
                          "r"(bh[nf][0]), "r"(bh[nf][1]));
                    asm volatile(
                        "mma.sync.aligned.m16n8k16.row.col.f32.bf16.bf16.f32 "
                        "{%0,%1,%2,%3}, {%4,%5,%6,%7}, {%8,%9}, {%0,%1,%2,%3};"
                        : "+f"(c[0]), "+f"(c[1]), "+f"(c[2]), "+f"(c[3])
                        : "r"(ah0), "r"(ah1), "r"(ah2), "r"(ah3),
                          "r"(bl[nf][0]), "r"(bl[nf][1]));
                    asm volatile(
                        "mma.sync.aligned.m16n8k16.row.col.f32.bf16.bf16.f32 "
                        "{%0,%1,%2,%3}, {%4,%5,%6,%7}, {%8,%9}, {%0,%1,%2,%3};"
                        : "+f"(c[0]), "+f"(c[1]), "+f"(c[2]), "+f"(c[3])
                        : "r"(al0), "r"(al1), "r"(al2), "r"(al3),
                          "r"(bh[nf][0]), "r"(bh[nf][1]));
                }
            }
        }
        __syncthreads();
    }

    int slot0 = (bx < 4) ? v : 4 + v;
    int colb = (bx & 3) * 128;
#pragma unroll
    for (int mf = 0; mf < 4; mf++) {
#pragma unroll
        for (int nf = 0; nf < 4; nf++) {
            int col = colb + wn * 32 + nf * 8 + tig * 2;
            int m0 = by * 128 + wm * 64 + mf * 16 + gq;
            int b2 = m0 >> 11, n2 = m0 & 2047;
            __half* dp = g_PQh + (((size_t)(b2 * 2048 + n2) * 8 + slot0) << 9) + col;
            *(__half2*)dp = __floats2half2_rn(acc[mf][nf][0], acc[mf][nf][1]);
            int m1 = m0 + 8;
            int b3 = m1 >> 11, n3 = m1 & 2047;
            __half* dp2 = g_PQh + (((size_t)(b3 * 2048 + n3) * 8 + slot0) << 9) + col;
            *(__half2*)dp2 = __floats2half2_rn(acc[mf][nf][2], acc[mf][nf][3]);
        }
    }
}

// ---------------------------------------------------------------------------
__global__ void __launch_bounds__(512) k_scores(const float* __restrict__ x,
                                                const float* __restrict__ W,
                                                const float* __restrict__ att) {
    __shared__ float shPQ[4096];
    __shared__ float shW[4096];
    __shared__ float shAtt[1024];
    int bi = blockIdx.x;
    int b = bi >> 11, n = bi & 2047;
    int tid = threadIdx.x;
    const __half2* pq = (const __half2*)(g_PQh + (((size_t)(b * 2048 + n)) << 12));
    for (int i = tid; i < 2048; i += 512) {
        float2 f = __half22float2(pq[i]);
        shPQ[2 * i] = f.x; shPQ[2 * i + 1] = f.y;
    }
    for (int i = tid; i < 2048; i += 512) {
        int j = i >> 9, o = i & 511;
        shW[i] = W[j * 512 + o];
        shW[2048 + i] = W[(128 + j) * 512 + o];
    }
    for (int i = tid; i < 1024; i += 512) shAtt[i] = att[i];
    __syncthreads();

    int c = tid >> 5, lane = tid & 31;
    int g = c >> 2, h = c & 3, r = g ^ h;
    float xh[4], xg[4];
#pragma unroll
    for (int j = 0; j < 4; j++) {
        xh[j] = x[(((b * 4 + h) * 2048 + n) << 7) + j];
        xg[j] = x[(((b * 4 + r) * 2048 + n) << 7) + j];
    }
    float c1 = (r & 1) ? -2.f : 0.f, c2 = (r & 2) ? -2.f : 0.f;
    float c3 = (h & 1) ? -2.f : 0.f, c4 = (h & 2) ? -2.f : 0.f;
    float sa = 0.f, sb = 0.f;
    for (int o = lane; o < 512; o += 32) {
        float hv = shPQ[h * 512 + o] + shPQ[(4 + r) * 512 + o]
                 + c1 * (xh[0] * shW[o]        + xh[2] * shW[1024 + o])
                 + c2 * (xh[1] * shW[512 + o]  + xh[3] * shW[1536 + o])
                 + c3 * (xg[0] * shW[2048 + o] + xg[2] * shW[3072 + o])
                 + c4 * (xg[1] * shW[2560 + o] + xg[3] * shW[3584 + o]);
        float l = hv > 0.f ? hv : 0.2f * hv;
        sa += shAtt[o] * l;
        sb += shAtt[512 + o] * l;
    }
#pragma unroll
    for (int off = 16; off; off >>= 1) {
        sa += __shfl_xor_sync(0xffffffffu, sa, off);
        sb += __shfl_xor_sync(0xffffffffu, sb, off);
    }
    if (lane == 0) {
        g_sA[(b * 16 + c) * 2048 + n] = sa;
        g_sB[(b * 16 + c) * 2048 + n] = sb;
    }
}

__global__ void __launch_bounds__(512) k_exp() {
    int bc = blockIdx.x >> 2, ch = blockIdx.x & 3;
    __shared__ float red[512];
    const float* sA = g_sA + bc * 2048;
    const float* sB = g_sB + bc * 2048;
    int tid = threadIdx.x;

    float ma = -1e30f, mb = -1e30f;
    for (int i = tid; i < NN; i += 512) {
        ma = fmaxf(ma, sA[i]);
        mb = fmaxf(mb, sB[i]);
    }
    red[tid] = ma; __syncthreads();
    for (int st = 256; st > 0; st >>= 1) {
        if (tid < st) red[tid] = fmaxf(red[tid], red[tid + st]);
        __syncthreads();
    }
    float mx = red[0]; __syncthreads();
    red[tid] = mb; __syncthreads();
    for (int st = 256; st > 0; st >>= 1) {
        if (tid < st) red[tid] = fmaxf(red[tid], red[tid + st]);
        __syncthreads();
    }
    mx += red[0]; __syncthreads();

    float* wt = g_wt + (size_t)bc * ETOT;
    float sum = 0.f;
    int e0 = ch * ECH;
#pragma unroll 4
    for (int k = 0; k < ECH / 512; k++) {
        int e = e0 + k * 512 + tid;
        float w = expf(sA[g_src[e]] + sB[g_dst[e]] - mx);
        wt[e] = w;
        sum += w;
    }
    red[tid] = sum; __syncthreads();
    for (int st = 256; st > 0; st >>= 1) {
        if (tid < st) red[tid] += red[tid + st];
        __syncthreads();
    }
    if (tid == 0) g_psum[bc * 4 + ch] = red[0];
}

__global__ void k_sumS() {
    int bc = threadIdx.x;
    float s = g_psum[bc * 4] + g_psum[bc * 4 + 1] + g_psum[bc * 4 + 2] + g_psum[bc * 4 + 3];
    g_invS[bc] = 1.f / s;
}

__global__ void __launch_bounds__(512) k_norm() {
    __shared__ float inv[32];
    if (threadIdx.x < 32) inv[threadIdx.x] = g_invS[threadIdx.x];
    __syncthreads();
    int t = blockIdx.x * 512 + threadIdx.x;
    int bc = t / ETOT;
    int e = t - bc * ETOT;
    g_w[(size_t)e * 32 + bc] = g_wt[t] * inv[bc];
}

__global__ void __launch_bounds__(64) k_coef(const float* __restrict__ x) {
    int d = blockIdx.x, tid = threadIdx.x;
    int b = tid >> 5, q = tid & 31;
    int g = q >> 3, j = q & 7, jj = j & 3, isB = j >> 2;
    int mask = (jj & 1) ? 2 : 1;
    float ca = 0.f;
    int beg = g_rowOff[d], end = g_rowOff[d + 1];
    for (int idx = beg; idx < end; idx++) {
        int e = g_csr[idx];
        int s = g_src[e];
#pragma unroll
        for (int h = 0; h < 4; h++) {
            int r = isB ? h : (g ^ h);
            if (r & mask) {
                int vsel = isB ? (g ^ h) : h;
                ca += g_w[(size_t)e * 32 + b * 16 + g * 4 + h]
                    * x[(((b * 4 + vsel) * 2048 + s) << 7) + jj];
            }
        }
    }
    g_coef[d * 64 + tid] = -2.f * ca;
}

// ---------------------------------------------------------------------------
// dst-centric aggregation: 128 threads x 4 cols, uint2 fp16 gathers.
__global__ void __launch_bounds__(128, 4) k_agg(const float* __restrict__ W,
                                                const float* __restrict__ bias,
                                                float* __restrict__ out) {
    int d = blockIdx.x;
    int tid = threadIdx.x, lane = tid & 31;
    __shared__ int sh_e[512];
    __shared__ int sh_s[512];
    __shared__ float sh_cf[64];

    int beg = g_rowOff[d];
    int deg = g_rowOff[d + 1] - beg;
    for (int i = tid; i < deg; i += 128) {
        int e = g_csr[beg + i];
        sh_e[i] = e;
        sh_s[i] = g_src[e];
    }
    if (tid < 64) sh_cf[tid] = g_coef[d * 64 + tid];
    __syncthreads();

    float acc[2][4][4];   // [b][g][col]
#pragma unroll
    for (int b = 0; b < 2; b++)
#pragma unroll
        for (int g = 0; g < 4; g++)
#pragma unroll
            for (int j = 0; j < 4; j++) acc[b][g][j] = 0.f;

    for (int i = 0; i < deg; i++) {
        int e = sh_e[i], s = sh_s[i];
        float wl = __ldg(g_w + (size_t)e * 32 + lane);
#pragma unroll
        for (int b = 0; b < 2; b++) {
            const uint2* base = (const uint2*)(g_PQh + (((size_t)(b * 2048 + s)) << 12)) + tid;
            float pc[4][4], qc[4][4];
#pragma unroll
            for (int h = 0; h < 4; h++) {
                uint2 u = __ldg(base + h * 128);
                float2 f0 = __half22float2(*(__half2*)&u.x);
                float2 f1 = __half22float2(*(__half2*)&u.y);
                pc[h][0] = f0.x; pc[h][1] = f0.y; pc[h][2] = f1.x; pc[h][3] = f1.y;
            }
#pragma unroll
            for (int h = 0; h < 4; h++) {
                uint2 u = __ldg(base + 512 + h * 128);
                float2 f0 = __half22float2(*(__half2*)&u.x);
                float2 f1 = __half22float2(*(__half2*)&u.y);
                qc[h][0] = f0.x; qc[h][1] = f0.y; qc[h][2] = f1.x; qc[h][3] = f1.y;
            }
#pragma unroll
            for (int g = 0; g < 4; g++)
#pragma unroll
                for (int h = 0; h < 4; h++) {
                    float w = __shfl_sync(0xffffffffu, wl, b * 16 + g * 4 + h);
                    int j2 = g ^ h;
#pragma unroll
                    for (int j = 0; j < 4; j++)
                        acc[b][g][j] = fmaf(w, pc[h][j] + qc[j2][j], acc[b][g][j]);
                }
        }
    }

    int c0 = 4 * tid;
    float4 wt[4], wb[4];
#pragma unroll
    for (int r = 0; r < 4; r++) {
        wt[r] = *(const float4*)(W + r * 512 + c0);
        wb[r] = *(const float4*)(W + (128 + r) * 512 + c0);
    }
    float4 bs = *(const float4*)(bias + c0);
#pragma unroll
    for (int b = 0; b < 2; b++)
#pragma unroll
        for (int g = 0; g < 4; g++) {
            const float* cf = sh_cf + b * 32 + g * 8;
            float4 o;
            o.x = acc[b][g][0] + cf[0]*wt[0].x + cf[1]*wt[1].x + cf[2]*wt[2].x + cf[3]*wt[3].x
                               + cf[4]*wb[0].x + cf[5]*wb[1].x + cf[6]*wb[2].x + cf[7]*wb[3].x;
            o.y = acc[b][g][1] + cf[0]*wt[0].y + cf[1]*wt[1].y + cf[2]*wt[2].y + cf[3]*wt[3].y
                               + cf[4]*wb[0].y + cf[5]*wb[1].y + cf[6]*wb[2].y + cf[7]*wb[3].y;
            o.z = acc[b][g][2] + cf[0]*wt[0].z + cf[1]*wt[1].z + cf[2]*wt[2].z + cf[3]*wt[3].z
                               + cf[4]*wb[0].z + cf[5]*wb[1].z + cf[6]*wb[2].z + cf[7]*wb[3].z;
            o.w = acc[b][g][3] + cf[0]*wt[0].w + cf[1]*wt[1].w + cf[2]*wt[2].w + cf[3]*wt[3].w
                               + cf[4]*wb[0].w + cf[5]*wb[1].w + cf[6]*wb[2].w + cf[7]*wb[3].w;
            o.x = 0.25f * o.x + bs.x; o.y = 0.25f * o.y + bs.y;
            o.z = 0.25f * o.z + bs.z; o.w = 0.25f * o.w + bs.w;
            *(float4*)(out + (((size_t)(b * 4 + g) * 2048 + d) << 9) + c0) = o;
        }
}

// ---------------------------------------------------------------------------
extern "C" void kernel_launch(void* const* d_in, const int* in_sizes, int n_in,
                              void* d_out, int out_size) {
    const float* x    = (const float*)d_in[0];
    const int*   ei   = (const int*)d_in[1];
    const float* W    = (const float*)d_in[2];
    const float* att  = (const float*)d_in[3];
    const float* bias = (const float*)d_in[4];
    float* out = (float*)d_out;

    // Lazily-created side stream + events (created on the non-captured
    // correctness call; every call performs the identical launch sequence).
    static cudaStream_t sCSR = nullptr;
    static cudaEvent_t evStart = nullptr, evHist = nullptr, evCSR = nullptr;
    if (!sCSR) {
        cudaStreamCreateWithFlags(&sCSR, cudaStreamNonBlocking);
        cudaEventCreateWithFlags(&evStart, cudaEventDisableTiming);
        cudaEventCreateWithFlags(&evHist, cudaEventDisableTiming);
        cudaEventCreateWithFlags(&evCSR, cudaEventDisableTiming);
    }

    // Fork: CSR chain on side stream
    cudaEventRecord(evStart, 0);
    cudaStreamWaitEvent(sCSR, evStart, 0);
    k_hist<<<NCH, CHK, 0, sCSR>>>(ei);
    cudaEventRecord(evHist, sCSR);
    k_chprefix<<<2, 1024, 0, sCSR>>>();
    k_scan<<<1, 1024, 0, sCSR>>>();
    k_scatter<<<NCH, CHK, 0, sCSR>>>();
    cudaEventRecord(evCSR, sCSR);

    // Main stream: dense path
    k_splitX<<<(BB * VV * NN * FF) / 256, 256>>>(x);
    k_splitW<<<(1024 * 128) / 256, 256>>>(W);
    k_gemm<<<dim3(8, 32, 4), 256>>>(0);
    k_scores<<<BB * NN, 512>>>(x, W, att);
    cudaStreamWaitEvent(0, evHist, 0);      // need g_src/g_dst
    k_exp<<<128, 512>>>();
    k_sumS<<<1, 32>>>();
    k_norm<<<(32 * ETOT) / 512, 512>>>();
    cudaStreamWaitEvent(0, evCSR, 0);       // need csr/rowOff
    k_coef<<<NN, 64>>>(x);
    k_agg<<<NN, 128>>>(W, bias, out);
}